// round 6
// baseline (speedup 1.0000x reference)
#include <cuda_runtime.h>
#include <cuda_bf16.h>
#include <math.h>
#include <stdint.h>

#define HC 128
#define NVMAX 50000
#define NEMAX 400000
#define NG 512
#define LAYERS 2
#define NW 24

// packed weight image: [n][k] bf16, row stride 136 (pad 8), hi then lo
#define WROW 136
#define WIMG_ELEMS (128 * WROW)            // 17408 bf16 per (hi|lo) image
#define WIMG_BYTES (WIMG_ELEMS * 2)        // 34816 B
#define WPAIR_BYTES (2 * WIMG_BYTES)       // 69632 B (hi+lo)

// ---------------- scratch (device globals; no allocation) ----------------
__device__ float g_xs0[NVMAX * HC];
__device__ float g_xs1[NVMAX * HC];
__device__ float g_tmp[NVMAX * HC];
__device__ float g_kt0[NVMAX * HC];
__device__ float g_vt0[NVMAX * HC];
__device__ float g_kt1[NVMAX * HC];
__device__ float g_vt1[NVMAX * HC];
__device__ float g_qe0[NVMAX * HC];   // Q of con nodes (dst of et=0)
__device__ float g_qe1[NVMAX * HC];   // Q of var nodes (dst of et=1)
__device__ float g_aggv[NVMAX * HC];
__device__ float g_aggc[NVMAX * HC];
__device__ float g_alpha[2 * NEMAX * 4];
__device__ float g_amaxv[NVMAX * 4];
__device__ float g_amaxc[NVMAX * 4];
__device__ float g_denv[NVMAX * 4];
__device__ float g_denc[NVMAX * 4];
__device__ __align__(16) __nv_bfloat16 g_wimg[NW * 2 * WIMG_ELEMS];
__device__ float g_bcomp[8 * HC];
__device__ float g_gsum[NG * 2];
__device__ float g_gcnt[NG];

// ---------------- helpers ----------------
__device__ __forceinline__ uint32_t smem_u32(const void* p) {
    uint32_t a;
    asm("{ .reg .u64 t; cvta.to.shared.u64 t, %1; cvt.u32.u64 %0, t; }" : "=r"(a) : "l"(p));
    return a;
}
__device__ __forceinline__ void bsplit(float x, __nv_bfloat16& h, __nv_bfloat16& l) {
    h = __float2bfloat16(x);
    l = __float2bfloat16(x - __bfloat162float(h));
}
__device__ __forceinline__ float gelu_exact(float x) {
    return 0.5f * x * (1.f + erff(x * 0.70710678118654752440f));
}
__device__ __forceinline__ void ldm_x4(uint32_t* r, uint32_t addr) {
    asm volatile("ldmatrix.sync.aligned.m8n8.x4.shared.b16 {%0,%1,%2,%3}, [%4];"
                 : "=r"(r[0]), "=r"(r[1]), "=r"(r[2]), "=r"(r[3]) : "r"(addr));
}
__device__ __forceinline__ void mma16816(float* c, const uint32_t* a, const uint32_t* b) {
    asm volatile("mma.sync.aligned.m16n8k16.row.col.f32.bf16.bf16.f32 "
                 "{%0,%1,%2,%3}, {%4,%5,%6,%7}, {%8,%9}, {%0,%1,%2,%3};"
                 : "+f"(c[0]), "+f"(c[1]), "+f"(c[2]), "+f"(c[3])
                 : "r"(a[0]), "r"(a[1]), "r"(a[2]), "r"(a[3]), "r"(b[0]), "r"(b[1]));
}
__device__ __forceinline__ void cp_async16(uint32_t saddr, const void* gaddr) {
    asm volatile("cp.async.cg.shared.global [%0], [%1], 16;" :: "r"(saddr), "l"(gaddr));
}

// ---------------- shared GEMM building blocks ----------------
// A tile convert: global fp32 [row0..row0+127][0..127] -> smem bf16 hi/lo [r][k] stride 136
template <bool NORM>
__device__ __forceinline__ void convert_A(const float* __restrict__ A, int row0, int N,
                                          char* smemA, const float* __restrict__ den,
                                          int tid) {
#pragma unroll
    for (int it = 0; it < 8; ++it) {
        int i = tid + it * 512;
        int r = i >> 5;
        int k = (i & 31) * 4;
        float4 av = make_float4(0.f, 0.f, 0.f, 0.f);
        int row = row0 + r;
        if (row < N) av = *(const float4*)(A + (size_t)row * HC + k);
        if (NORM) {
            float rcp = 1.f / fmaxf(den[(size_t)row * 4 + (k >> 5)], 1e-37f);
            av.x = gelu_exact(av.x * rcp); av.y = gelu_exact(av.y * rcp);
            av.z = gelu_exact(av.z * rcp); av.w = gelu_exact(av.w * rcp);
        }
        __nv_bfloat162 h01 = __float22bfloat162_rn(make_float2(av.x, av.y));
        __nv_bfloat162 h23 = __float22bfloat162_rn(make_float2(av.z, av.w));
        float2 f01 = __bfloat1622float2(h01);
        float2 f23 = __bfloat1622float2(h23);
        __nv_bfloat162 l01 = __float22bfloat162_rn(make_float2(av.x - f01.x, av.y - f01.y));
        __nv_bfloat162 l23 = __float22bfloat162_rn(make_float2(av.z - f23.x, av.w - f23.y));
        uint32_t off = (uint32_t)(r * WROW + k) * 2;
        *(uint2*)(smemA + off) = make_uint2(*(uint32_t*)&h01, *(uint32_t*)&h23);
        *(uint2*)(smemA + WIMG_BYTES + off) = make_uint2(*(uint32_t*)&l01, *(uint32_t*)&l23);
    }
}

// 3-pass error-compensated 128x128x128 MMA; a_lane/b_lane = per-lane smem addrs of hi images
__device__ __forceinline__ void mma_tile3(uint32_t a_lane, uint32_t b_lane, float acc[2][4][4]) {
#pragma unroll
    for (int i = 0; i < 2; i++)
#pragma unroll
        for (int j = 0; j < 4; j++)
#pragma unroll
            for (int q = 0; q < 4; q++) acc[i][j][q] = 0.f;
#pragma unroll
    for (int p = 0; p < 3; p++) {
        uint32_t abase = a_lane + (p == 2 ? (uint32_t)WIMG_BYTES : 0u);
        uint32_t bbase = b_lane + (p == 1 ? (uint32_t)WIMG_BYTES : 0u);
#pragma unroll
        for (int ks = 0; ks < 8; ks++) {
            uint32_t ar[2][4], br[2][4];
            ldm_x4(ar[0], abase + ks * 32);
            ldm_x4(ar[1], abase + ks * 32 + 16 * WROW * 2);
            ldm_x4(br[0], bbase + ks * 32);
            ldm_x4(br[1], bbase + ks * 32 + 16 * WROW * 2);
#pragma unroll
            for (int mt = 0; mt < 2; mt++) {
                mma16816(acc[mt][0], ar[mt], br[0] + 0);
                mma16816(acc[mt][1], ar[mt], br[0] + 2);
                mma16816(acc[mt][2], ar[mt], br[1] + 0);
                mma16816(acc[mt][3], ar[mt], br[1] + 2);
            }
        }
    }
}

#define EPI_NONE 0
#define EPI_RELU 1
#define EPI_GATED 2

template <int EPI>
__device__ __forceinline__ void epilogue(float acc[2][4][4], const float* __restrict__ bias,
                                         float* __restrict__ C, const float* __restrict__ xprev,
                                         float g, float og, int row0, int N,
                                         int warpM, int warpN, int gid, int tq) {
#pragma unroll
    for (int mt = 0; mt < 2; mt++) {
#pragma unroll
        for (int nt = 0; nt < 4; nt++) {
            int col = warpN * 32 + nt * 8 + tq * 2;
            float2 bv = *(const float2*)(bias + col);
#pragma unroll
            for (int half = 0; half < 2; half++) {
                int row = row0 + warpM * 32 + mt * 16 + gid + half * 8;
                if (row >= N) continue;
                float c0 = acc[mt][nt][half * 2 + 0] + bv.x;
                float c1 = acc[mt][nt][half * 2 + 1] + bv.y;
                if (EPI == EPI_RELU) { c0 = fmaxf(c0, 0.f); c1 = fmaxf(c1, 0.f); }
                if (EPI == EPI_GATED) {
                    float2 xp = *(const float2*)(xprev + (size_t)row * HC + col);
                    c0 = g * c0 + og * xp.x;
                    c1 = g * c1 + og * xp.y;
                }
                *(float2*)(C + (size_t)row * HC + col) = make_float2(c0, c1);
            }
        }
    }
}

// ---------------- weight pre-pack (compose + split, [n][k] stride-136) ------
struct PackJobs {
    const float* w[NW];
    const float* rel[NW];
    const float* bin[NW];
    float* bout[NW];
};

__global__ void pack_kernel(PackJobs jobs, __nv_bfloat16* img) {
    int j = blockIdx.x;
    int part = blockIdx.y;
    int tid = threadIdx.x;
    const float* w = jobs.w[j];
    const float* rel = jobs.rel[j];
    __shared__ float rs[4096];
    if (rel) {
        for (int i = tid; i < 4096; i += 256) rs[i] = rel[i];
        __syncthreads();
    }
    __nv_bfloat16* ih = img + (size_t)j * 2 * WIMG_ELEMS;
    __nv_bfloat16* il = ih + WIMG_ELEMS;
    for (int idx = part * 4096 + tid; idx < (part + 1) * 4096; idx += 256) {
        int k = idx >> 7, n = idx & 127;
        float val;
        if (rel) {
            int h = n >> 5, nn = n & 31;
            const float* wr = w + k * 128 + h * 32;
            const float* rr = rs + h * 1024 + nn;
            float s = 0.f;
#pragma unroll
            for (int jj = 0; jj < 32; jj++) s += wr[jj] * rr[jj * 32];
            val = s;
        } else {
            val = w[k * 128 + n];
        }
        __nv_bfloat16 h, l;
        bsplit(val, h, l);
        ih[n * WROW + k] = h;
        il[n * WROW + k] = l;
    }
    if (part == 0 && rel && jobs.bout[j] && tid < 128) {
        int h = tid >> 5, nn = tid & 31;
        const float* b = jobs.bin[j];
        float s = 0.f;
#pragma unroll
        for (int jj = 0; jj < 32; jj++) s += b[h * 32 + jj] * rs[h * 1024 + jj * 32 + nn];
        jobs.bout[j][tid] = s;
    }
}

// ---------------- two-segment GEMM (input MLPs / gated update / head) --------
#define SM2_A 0
#define SM2_W WPAIR_BYTES
#define SMEM_MM2 (2 * WPAIR_BYTES)    // 139264

struct Mm2P {
    const float* A[2];
    const __nv_bfloat16* W[2];
    const float* bias[2];
    float* C[2];
    const float* gate[2];
    const float* xprev[2];
    const float* den[2];
    int N[2];
    int T0;
};

template <bool NORM, int EPI>
__global__ void __launch_bounds__(512, 1)
mm2_kernel(Mm2P P) {
    extern __shared__ char smem[];
    int tid = threadIdx.x;
    int wid = tid >> 5;
    int lane = tid & 31;
    int bid = blockIdx.x;
    int seg = bid >= P.T0;
    int row0 = (seg ? (bid - P.T0) : bid) * 128;
    const float* A = P.A[seg];
    int N = P.N[seg];
    uint32_t sb = smem_u32(smem);

    for (int j = 0; j < 9; j++) {
        int i = tid + j * 512;
        if (i < 4352) cp_async16(sb + SM2_W + i * 16, (const float4*)P.W[seg] + i);
    }
    asm volatile("cp.async.commit_group;" ::: "memory");

    convert_A<NORM>(A, row0, N, smem + SM2_A, P.den[seg], tid);

    asm volatile("cp.async.wait_group 0;" ::: "memory");
    __syncthreads();

    int warpM = wid >> 2;
    int warpN = wid & 3;
    uint32_t a_lane = sb + SM2_A +
        ((uint32_t)((warpM * 32 + (lane & 15)) * WROW + ((lane >> 4) << 3)) << 1);
    uint32_t b_lane = sb + SM2_W +
        ((uint32_t)((warpN * 32 + (lane & 7) + ((lane >> 4) << 3)) * WROW +
                    (((lane >> 3) & 1) << 3)) << 1);

    float acc[2][4][4];
    mma_tile3(a_lane, b_lane, acc);

    float g = 0.f, og = 0.f;
    if (EPI == EPI_GATED) { g = 1.f / (1.f + expf(-*P.gate[seg])); og = 1.f - g; }
    epilogue<EPI>(acc, P.bias[seg], P.C[seg], P.xprev[seg], g, og, row0, N,
                  warpM, warpN, lane >> 2, lane & 3);
}

// ---------------- layer projection megakernel (K,V,Q for both types) ---------
#define SMP_A 0
#define SMP_W0 WPAIR_BYTES
#define SMP_W1 (2 * WPAIR_BYTES)
#define SMEM_PROJ (3 * WPAIR_BYTES)   // 208896

struct ProjP {
    const float* A[4];
    const __nv_bfloat16* W0[4];
    const __nv_bfloat16* W1[4];     // null if nout==1
    const float* b0[4];
    const float* b1[4];
    float* C0[4];
    float* C1[4];
    int N[4];
    int base[4];                     // ascending CTA base per group
    int nout[4];
};

__global__ void __launch_bounds__(512, 1)
proj_kernel(ProjP P) {
    extern __shared__ char smem[];
    int tid = threadIdx.x;
    int wid = tid >> 5;
    int lane = tid & 31;
    int bid = blockIdx.x;
    int g = 3;
    if (bid < P.base[3]) g = 2;
    if (bid < P.base[2]) g = 1;
    if (bid < P.base[1]) g = 0;
    int row0 = (bid - P.base[g]) * 128;
    const float* A = P.A[g];
    int N = P.N[g];
    int nout = P.nout[g];
    uint32_t sb = smem_u32(smem);

    for (int j = 0; j < 9; j++) {
        int i = tid + j * 512;
        if (i < 4352) cp_async16(sb + SMP_W0 + i * 16, (const float4*)P.W0[g] + i);
    }
    asm volatile("cp.async.commit_group;" ::: "memory");

    convert_A<false>(A, row0, N, smem + SMP_A, nullptr, tid);

    asm volatile("cp.async.wait_group 0;" ::: "memory");
    __syncthreads();

    int warpM = wid >> 2;
    int warpN = wid & 3;
    uint32_t a_lane = sb + SMP_A +
        ((uint32_t)((warpM * 32 + (lane & 15)) * WROW + ((lane >> 4) << 3)) << 1);
    uint32_t lane_off =
        ((uint32_t)((warpN * 32 + (lane & 7) + ((lane >> 4) << 3)) * WROW +
                    (((lane >> 3) & 1) << 3)) << 1);

    float acc[2][4][4];
    mma_tile3(a_lane, sb + SMP_W0 + lane_off, acc);

    if (nout == 2) {
        // prefetch W1 while epilogue of out0 runs
        for (int j = 0; j < 9; j++) {
            int i = tid + j * 512;
            if (i < 4352) cp_async16(sb + SMP_W1 + i * 16, (const float4*)P.W1[g] + i);
        }
        asm volatile("cp.async.commit_group;" ::: "memory");
    }

    epilogue<EPI_NONE>(acc, P.b0[g], P.C0[g], nullptr, 0.f, 0.f, row0, N,
                       warpM, warpN, lane >> 2, lane & 3);

    if (nout == 2) {
        asm volatile("cp.async.wait_group 0;" ::: "memory");
        __syncthreads();
        mma_tile3(a_lane, sb + SMP_W1 + lane_off, acc);
        epilogue<EPI_NONE>(acc, P.b1[g], P.C1[g], nullptr, 0.f, 0.f, row0, N,
                           warpM, warpN, lane >> 2, lane & 3);
    }
}

// ---------------- small utility kernels ----------------
__global__ void fill_kernel(float* __restrict__ p, float v, int n) {
    int i = blockIdx.x * blockDim.x + threadIdx.x;
    if (i < n) p[i] = v;
}

// clears both dst types' amax/den/agg in one launch
__global__ void attn_clear_kernel(float* av, float* dv, float* gv, int Nv,
                                  float* ac, float* dc, float* gc, int Nc) {
    int i = blockIdx.x * blockDim.x + threadIdx.x;
    if (i < Nv * 4) { av[i] = -INFINITY; dv[i] = 0.f; }
    if (i < Nc * 4) { ac[i] = -INFINITY; dc[i] = 0.f; }
    if (i < Nv * HC) gv[i] = 0.f;
    if (i < Nc * HC) gc[i] = 0.f;
}

// ---------------- attention kernels (both edge types fused per launch) -------
__device__ __forceinline__ void atomicMaxFloat(float* addr, float value) {
    if (value >= 0.f)
        atomicMax((int*)addr, __float_as_int(value));
    else
        atomicMin((unsigned int*)addr, __float_as_uint(value));
}

struct AttnP {
    const float* q[2];
    const float* kt[2];
    const float* vt[2];
    const int* src[2];
    const int* dst[2];
    const float* prel[2];
    float* alpha[2];
    float* amax[2];
    float* den[2];
    float* agg[2];
    int E0, Etot;
};

__global__ void attn_alpha_kernel(AttnP P) {
    int e = blockIdx.x * 8 + (threadIdx.x >> 5);
    if (e >= P.Etot) return;
    int seg = e >= P.E0;
    int el = e - (seg ? P.E0 : 0);
    int lane = threadIdx.x & 31;
    int s = P.src[seg][el], d = P.dst[seg][el];
    float4 qv = *(const float4*)(P.q[seg] + (size_t)d * HC + lane * 4);
    float4 kv = *(const float4*)(P.kt[seg] + (size_t)s * HC + lane * 4);
    float p = qv.x * kv.x + qv.y * kv.y + qv.z * kv.z + qv.w * kv.w;
    p += __shfl_xor_sync(0xffffffffu, p, 1);
    p += __shfl_xor_sync(0xffffffffu, p, 2);
    p += __shfl_xor_sync(0xffffffffu, p, 4);
    if (lane == 0) {
        float p1 = __shfl_sync(0xffffffffu, p, 8);
        float p2 = __shfl_sync(0xffffffffu, p, 16);
        float p3 = __shfl_sync(0xffffffffu, p, 24);
        float4 pr = *(const float4*)P.prel[seg];
        float4 a;
        a.x = p * pr.x * 0.17677669529663687f;
        a.y = p1 * pr.y * 0.17677669529663687f;
        a.z = p2 * pr.z * 0.17677669529663687f;
        a.w = p3 * pr.w * 0.17677669529663687f;
        *(float4*)(P.alpha[seg] + (size_t)el * 4) = a;
        float* am = P.amax[seg] + (size_t)d * 4;
        atomicMaxFloat(am + 0, a.x);
        atomicMaxFloat(am + 1, a.y);
        atomicMaxFloat(am + 2, a.z);
        atomicMaxFloat(am + 3, a.w);
    }
}

__global__ void attn_exp_kernel(AttnP P) {
    int e = blockIdx.x * blockDim.x + threadIdx.x;
    if (e >= P.Etot) return;
    int seg = e >= P.E0;
    int el = e - (seg ? P.E0 : 0);
    int d = P.dst[seg][el];
    float4 am = *(const float4*)(P.amax[seg] + (size_t)d * 4);
    float4 al = *(float4*)(P.alpha[seg] + (size_t)el * 4);
    float4 ex;
    ex.x = expf(al.x - am.x);
    ex.y = expf(al.y - am.y);
    ex.z = expf(al.z - am.z);
    ex.w = expf(al.w - am.w);
    *(float4*)(P.alpha[seg] + (size_t)el * 4) = ex;
    atomicAdd((float4*)(P.den[seg] + (size_t)d * 4), ex);
}

__global__ void attn_scatter_kernel(AttnP P) {
    int e = blockIdx.x * 8 + (threadIdx.x >> 5);
    if (e >= P.Etot) return;
    int seg = e >= P.E0;
    int el = e - (seg ? P.E0 : 0);
    int lane = threadIdx.x & 31;
    int s = P.src[seg][el], d = P.dst[seg][el];
    int h = lane >> 3;
    float w = P.alpha[seg][(size_t)el * 4 + h];
    float4 vv = *(const float4*)(P.vt[seg] + (size_t)s * HC + lane * 4);
    vv.x *= w; vv.y *= w; vv.z *= w; vv.w *= w;
    atomicAdd((float4*)(P.agg[seg] + (size_t)d * HC + lane * 4), vv);
}

// ---------------- output head ----------------
__global__ void out_head_kernel(const float* __restrict__ X, const float* __restrict__ W2,
                                const float* __restrict__ b2, const int* __restrict__ batch,
                                float* __restrict__ gsum, float* __restrict__ gcnt, int N) {
    int n = blockIdx.x * 8 + (threadIdx.x >> 5);
    if (n >= N) return;
    int lane = threadIdx.x & 31;
    float4 x = *(const float4*)(X + (size_t)n * HC + lane * 4);
    float4 wa = *(const float4*)(W2 + lane * 8);
    float4 wb = *(const float4*)(W2 + lane * 8 + 4);
    float p0 = x.x * wa.x + x.y * wa.z + x.z * wb.x + x.w * wb.z;
    float p1 = x.x * wa.y + x.y * wa.w + x.z * wb.y + x.w * wb.w;
#pragma unroll
    for (int off = 16; off > 0; off >>= 1) {
        p0 += __shfl_xor_sync(0xffffffffu, p0, off);
        p1 += __shfl_xor_sync(0xffffffffu, p1, off);
    }
    if (lane == 0) {
        float l0 = p0 + b2[0], l1 = p1 + b2[1];
        float m = fmaxf(l0, l1);
        float e0 = expf(l0 - m), e1 = expf(l1 - m);
        float inv = 1.f / (e0 + e1);
        int g = batch[n];
        atomicAdd(&gsum[g * 2 + 0], e0 * inv);
        atomicAdd(&gsum[g * 2 + 1], e1 * inv);
        atomicAdd(&gcnt[g], 1.f);
    }
}

__global__ void finalize_kernel(const float* __restrict__ gsum, const float* __restrict__ gcnt,
                                float* __restrict__ out, int G) {
    int g = blockIdx.x * blockDim.x + threadIdx.x;
    if (g >= G) return;
    float c = fmaxf(gcnt[g], 1.f);
    out[g * 2 + 0] = gsum[g * 2 + 0] / c;
    out[g * 2 + 1] = gsum[g * 2 + 1] / c;
}

// ---------------- host orchestration ----------------
static inline void fillf(float* p, float v, int n) {
    fill_kernel<<<(n + 255) / 256, 256>>>(p, v, n);
}

extern "C" void kernel_launch(void* const* d_in, const int* in_sizes, int n_in,
                              void* d_out, int out_size) {
    const float* x_var = (const float*)d_in[0];
    const float* x_con = (const float*)d_in[1];
    const float* mlp_in_w = (const float*)d_in[2];
    const float* mlp_in_b = (const float*)d_in[3];
    const float* w0 = (const float*)d_in[4];
    const float* b0 = (const float*)d_in[5];
    const float* w1 = (const float*)d_in[6];
    const float* b1 = (const float*)d_in[7];
    const float* w2 = (const float*)d_in[8];
    const float* b2 = (const float*)d_in[9];
    const float* k_w = (const float*)d_in[10];
    const float* k_b = (const float*)d_in[11];
    const float* q_w = (const float*)d_in[12];
    const float* q_b = (const float*)d_in[13];
    const float* v_w = (const float*)d_in[14];
    const float* v_b = (const float*)d_in[15];
    const float* a_w = (const float*)d_in[16];
    const float* a_b = (const float*)d_in[17];
    const float* skip = (const float*)d_in[18];
    const float* a_rel = (const float*)d_in[19];
    const float* m_rel = (const float*)d_in[20];
    const float* p_rel = (const float*)d_in[21];
    const int* evc = (const int*)d_in[22];
    const int* ecv = (const int*)d_in[23];
    const int* batch = (const int*)d_in[24];
    float* out = (float*)d_out;

    int Nv = in_sizes[0] / HC;
    int Nc = in_sizes[1] / HC;
    int Evc = in_sizes[22] / 2;
    int Ecv = in_sizes[23] / 2;
    int Tv = (Nv + 127) / 128;
    int Tc = (Nc + 127) / 128;

    float *xs0, *xs1, *tmp, *kt0, *vt0, *kt1, *vt1, *qe0, *qe1, *aggv, *aggc;
    float *alpha, *amaxv, *amaxc, *denv, *denc, *bcomp, *gsum, *gcnt;
    __nv_bfloat16* wimg;
    cudaGetSymbolAddress((void**)&xs0, g_xs0);
    cudaGetSymbolAddress((void**)&xs1, g_xs1);
    cudaGetSymbolAddress((void**)&tmp, g_tmp);
    cudaGetSymbolAddress((void**)&kt0, g_kt0);
    cudaGetSymbolAddress((void**)&vt0, g_vt0);
    cudaGetSymbolAddress((void**)&kt1, g_kt1);
    cudaGetSymbolAddress((void**)&vt1, g_vt1);
    cudaGetSymbolAddress((void**)&qe0, g_qe0);
    cudaGetSymbolAddress((void**)&qe1, g_qe1);
    cudaGetSymbolAddress((void**)&aggv, g_aggv);
    cudaGetSymbolAddress((void**)&aggc, g_aggc);
    cudaGetSymbolAddress((void**)&alpha, g_alpha);
    cudaGetSymbolAddress((void**)&amaxv, g_amaxv);
    cudaGetSymbolAddress((void**)&amaxc, g_amaxc);
    cudaGetSymbolAddress((void**)&denv, g_denv);
    cudaGetSymbolAddress((void**)&denc, g_denc);
    cudaGetSymbolAddress((void**)&wimg, g_wimg);
    cudaGetSymbolAddress((void**)&bcomp, g_bcomp);
    cudaGetSymbolAddress((void**)&gsum, g_gsum);
    cudaGetSymbolAddress((void**)&gcnt, g_gcnt);

    cudaFuncSetAttribute(mm2_kernel<false, EPI_NONE>,
                         cudaFuncAttributeMaxDynamicSharedMemorySize, SMEM_MM2);
    cudaFuncSetAttribute(mm2_kernel<false, EPI_RELU>,
                         cudaFuncAttributeMaxDynamicSharedMemorySize, SMEM_MM2);
    cudaFuncSetAttribute(mm2_kernel<true, EPI_GATED>,
                         cudaFuncAttributeMaxDynamicSharedMemorySize, SMEM_MM2);
    cudaFuncSetAttribute(proj_kernel,
                         cudaFuncAttributeMaxDynamicSharedMemorySize, SMEM_PROJ);

    // ---- weight packing ----
    // 0..5 input MLP (type-major), 6..9 composed K (li), 10..13 composed V (li),
    // 14..17 Q (li), 18..21 a_w (li), 22,23 head w0,w1
    PackJobs pj;
    for (int j = 0; j < NW; j++) { pj.w[j] = nullptr; pj.rel[j] = nullptr; pj.bin[j] = nullptr; pj.bout[j] = nullptr; }
    for (int t = 0; t < 2; t++)
        for (int i = 0; i < 3; i++) pj.w[t * 3 + i] = mlp_in_w + (size_t)(t * 3 + i) * 16384;
    for (int li = 0; li < 4; li++) {
        pj.w[6 + li] = k_w + (size_t)li * 16384;
        pj.rel[6 + li] = a_rel + (size_t)li * 4096;
        pj.bin[6 + li] = k_b + (size_t)li * 128;
        pj.bout[6 + li] = bcomp + (size_t)li * 128;
        pj.w[10 + li] = v_w + (size_t)li * 16384;
        pj.rel[10 + li] = m_rel + (size_t)li * 4096;
        pj.bin[10 + li] = v_b + (size_t)li * 128;
        pj.bout[10 + li] = bcomp + (size_t)(4 + li) * 128;
        pj.w[14 + li] = q_w + (size_t)li * 16384;
        pj.w[18 + li] = a_w + (size_t)li * 16384;
    }
    pj.w[22] = w0;
    pj.w[23] = w1;
    pack_kernel<<<dim3(NW, 4), 256>>>(pj, wimg);

#define IMG(j) (wimg + (size_t)(j) * 2 * WIMG_ELEMS)

    // ---- input MLPs: 3 two-segment launches ----
    for (int i = 0; i < 3; i++) {
        Mm2P m{};
        m.A[0] = (i == 0) ? x_var : xs0;  m.A[1] = (i == 0) ? x_con : xs1;
        m.W[0] = IMG(i);                   m.W[1] = IMG(3 + i);
        m.bias[0] = mlp_in_b + (size_t)i * 128;
        m.bias[1] = mlp_in_b + (size_t)(3 + i) * 128;
        m.C[0] = xs0; m.C[1] = xs1;
        m.N[0] = Nv; m.N[1] = Nc; m.T0 = Tv;
        if (i < 2)
            mm2_kernel<false, EPI_RELU><<<Tv + Tc, 512, SMEM_MM2>>>(m);
        else
            mm2_kernel<false, EPI_NONE><<<Tv + Tc, 512, SMEM_MM2>>>(m);
    }

    // ---- HGTConv layers ----
    for (int l = 0; l < LAYERS; l++) {
        int li0 = l * 2 + 0, li1 = l * 2 + 1;

        // projections: all 6 GEMMs in one launch
        ProjP pp{};
        // g0: xs0 -> kt0, vt0
        pp.A[0] = xs0; pp.N[0] = Nv; pp.nout[0] = 2;
        pp.W0[0] = IMG(6 + li0); pp.W1[0] = IMG(10 + li0);
        pp.b0[0] = bcomp + (size_t)li0 * 128; pp.b1[0] = bcomp + (size_t)(4 + li0) * 128;
        pp.C0[0] = kt0; pp.C1[0] = vt0;
        // g1: xs1 -> kt1, vt1
        pp.A[1] = xs1; pp.N[1] = Nc; pp.nout[1] = 2;
        pp.W0[1] = IMG(6 + li1); pp.W1[1] = IMG(10 + li1);
        pp.b0[1] = bcomp + (size_t)li1 * 128; pp.b1[1] = bcomp + (size_t)(4 + li1) * 128;
        pp.C0[1] = kt1; pp.C1[1] = vt1;
        // g2: xs1 -> qe0 (dst type of et=0 is con)
        pp.A[2] = xs1; pp.N[2] = Nc; pp.nout[2] = 1;
        pp.W0[2] = IMG(14 + li1); pp.W1[2] = nullptr;
        pp.b0[2] = q_b + (size_t)li1 * 128; pp.b1[2] = nullptr;
        pp.C0[2] = qe0; pp.C1[2] = nullptr;
        // g3: xs0 -> qe1 (dst type of et=1 is var)
        pp.A[3] = xs0; pp.N[3] = Nv; pp.nout[3] = 1;
        pp.W0[3] = IMG(14 + li0); pp.W1[3] = nullptr;
        pp.b0[3] = q_b + (size_t)li0 * 128; pp.b1[3] = nullptr;
        pp.C0[3] = qe1; pp.C1[3] = nullptr;
        pp.base[0] = 0; pp.base[1] = Tv; pp.base[2] = Tv + Tc; pp.base[3] = Tv + 2 * Tc;
        int totalT = 2 * Tv + 2 * Tc;
        proj_kernel<<<totalT, 512, SMEM_PROJ>>>(pp);

        // clear both dst types
        {
            int mx = (Nv > Nc ? Nv : Nc) * HC;
            attn_clear_kernel<<<(mx + 255) / 256, 256>>>(amaxv, denv, aggv, Nv,
                                                         amaxc, denc, aggc, Nc);
        }

        // fused attention (both edge types)
        AttnP ap{};
        // seg0: et=0 var->con
        ap.q[0] = qe0; ap.kt[0] = kt0; ap.vt[0] = vt0;
        ap.src[0] = evc; ap.dst[0] = evc + Evc;
        ap.prel[0] = p_rel + (size_t)li0 * 4;
        ap.alpha[0] = alpha; ap.amax[0] = amaxc; ap.den[0] = denc; ap.agg[0] = aggc;
        // seg1: et=1 con->var
        ap.q[1] = qe1; ap.kt[1] = kt1; ap.vt[1] = vt1;
        ap.src[1] = ecv; ap.dst[1] = ecv + Ecv;
        ap.prel[1] = p_rel + (size_t)li1 * 4;
        ap.alpha[1] = alpha + (size_t)Evc * 4; ap.amax[1] = amaxv; ap.den[1] = denv; ap.agg[1] = aggv;
        ap.E0 = Evc; ap.Etot = Evc + Ecv;
        attn_alpha_kernel<<<(ap.Etot + 7) / 8, 256>>>(ap);
        attn_exp_kernel<<<(ap.Etot + 255) / 256, 256>>>(ap);
        attn_scatter_kernel<<<(ap.Etot + 7) / 8, 256>>>(ap);

        // gated update (both node types, one launch)
        Mm2P gm{};
        gm.A[0] = aggv; gm.A[1] = aggc;
        gm.W[0] = IMG(18 + li0); gm.W[1] = IMG(18 + li1);
        gm.bias[0] = a_b + (size_t)li0 * 128; gm.bias[1] = a_b + (size_t)li1 * 128;
        gm.C[0] = xs0; gm.C[1] = xs1;
        gm.gate[0] = skip + li0; gm.gate[1] = skip + li1;
        gm.xprev[0] = xs0; gm.xprev[1] = xs1;
        gm.den[0] = denv; gm.den[1] = denc;
        gm.N[0] = Nv; gm.N[1] = Nc; gm.T0 = Tv;
        mm2_kernel<true, EPI_GATED><<<Tv + Tc, 512, SMEM_MM2>>>(gm);
    }

    // ---- output head ----
    for (int i = 0; i < 2; i++) {
        Mm2P m{};
        m.A[0] = (i == 0) ? xs0 : tmp; m.A[1] = m.A[0];
        m.W[0] = IMG(22 + i); m.W[1] = m.W[0];
        m.bias[0] = (i == 0) ? b0 : b1; m.bias[1] = m.bias[0];
        m.C[0] = tmp; m.C[1] = tmp;
        m.N[0] = Nv; m.N[1] = 0; m.T0 = Tv;
        mm2_kernel<false, EPI_RELU><<<Tv, 512, SMEM_MM2>>>(m);
    }
    fillf(gsum, 0.f, NG * 2);
    fillf(gcnt, 0.f, NG);
    out_head_kernel<<<(Nv + 7) / 8, 256>>>(tmp, w2, b2, batch, gsum, gcnt, Nv);
    finalize_kernel<<<(NG + 255) / 256, 256>>>(gsum, gcnt, out, NG);
}

// round 7
// speedup vs baseline: 1.1480x; 1.1480x over previous
#include <cuda_runtime.h>
#include <cuda_bf16.h>
#include <math.h>
#include <stdint.h>

#define HC 128
#define NVMAX 50000
#define NEMAX 400000
#define NG 512
#define LAYERS 2
#define NW 24

// packed weight image: [n][k] bf16, row stride 136 (pad 8), hi then lo
#define WROW 136
#define WIMG_ELEMS (128 * WROW)            // 17408 bf16 per (hi|lo) image
#define WIMG_BYTES (WIMG_ELEMS * 2)        // 34816 B
// A tile: 64 rows
#define AIMG_BYTES (64 * WROW * 2)         // 17408 B per (hi|lo)

// ---------------- scratch (device globals; no allocation) ----------------
__device__ float g_xs0[NVMAX * HC];
__device__ float g_xs1[NVMAX * HC];
__device__ float g_tmp[NVMAX * HC];
__device__ float g_kt0[NVMAX * HC];
__device__ float g_vt0[NVMAX * HC];
__device__ float g_kt1[NVMAX * HC];
__device__ float g_vt1[NVMAX * HC];
__device__ float g_qe0[NVMAX * HC];   // Q of con nodes (dst of et=0)
__device__ float g_qe1[NVMAX * HC];   // Q of var nodes (dst of et=1)
__device__ float g_aggv[NVMAX * HC];
__device__ float g_aggc[NVMAX * HC];
__device__ float g_alpha[2 * NEMAX * 4];
__device__ float g_denv[NVMAX * 4];
__device__ float g_denc[NVMAX * 4];
__device__ __align__(16) __nv_bfloat16 g_wimg[NW * 2 * WIMG_ELEMS];
__device__ float g_bcomp[8 * HC];
__device__ float g_gsum[NG * 2];
__device__ float g_gcnt[NG];

// ---------------- helpers ----------------
__device__ __forceinline__ uint32_t smem_u32(const void* p) {
    uint32_t a;
    asm("{ .reg .u64 t; cvta.to.shared.u64 t, %1; cvt.u32.u64 %0, t; }" : "=r"(a) : "l"(p));
    return a;
}
__device__ __forceinline__ void bsplit(float x, __nv_bfloat16& h, __nv_bfloat16& l) {
    h = __float2bfloat16(x);
    l = __float2bfloat16(x - __bfloat162float(h));
}
__device__ __forceinline__ float gelu_exact(float x) {
    return 0.5f * x * (1.f + erff(x * 0.70710678118654752440f));
}
__device__ __forceinline__ void ldm_x4(uint32_t* r, uint32_t addr) {
    asm volatile("ldmatrix.sync.aligned.m8n8.x4.shared.b16 {%0,%1,%2,%3}, [%4];"
                 : "=r"(r[0]), "=r"(r[1]), "=r"(r[2]), "=r"(r[3]) : "r"(addr));
}
__device__ __forceinline__ void mma16816(float* c, const uint32_t* a, const uint32_t* b) {
    asm volatile("mma.sync.aligned.m16n8k16.row.col.f32.bf16.bf16.f32 "
                 "{%0,%1,%2,%3}, {%4,%5,%6,%7}, {%8,%9}, {%0,%1,%2,%3};"
                 : "+f"(c[0]), "+f"(c[1]), "+f"(c[2]), "+f"(c[3])
                 : "r"(a[0]), "r"(a[1]), "r"(a[2]), "r"(a[3]), "r"(b[0]), "r"(b[1]));
}
__device__ __forceinline__ void cp_async16(uint32_t saddr, const void* gaddr) {
    asm volatile("cp.async.cg.shared.global [%0], [%1], 16;" :: "r"(saddr), "l"(gaddr));
}

// ---------------- weight pre-pack (compose + split, [n][k] stride-136) ------
struct PackJobs {
    const float* w[NW];
    const float* rel[NW];
    const float* bin[NW];
    float* bout[NW];
};

__global__ void pack_kernel(PackJobs jobs, __nv_bfloat16* img) {
    int j = blockIdx.x;
    int part = blockIdx.y;
    int tid = threadIdx.x;
    const float* w = jobs.w[j];
    const float* rel = jobs.rel[j];
    __shared__ float rs[4096];
    if (rel) {
        for (int i = tid; i < 4096; i += 256) rs[i] = rel[i];
        __syncthreads();
    }
    __nv_bfloat16* ih = img + (size_t)j * 2 * WIMG_ELEMS;
    __nv_bfloat16* il = ih + WIMG_ELEMS;
    for (int idx = part * 4096 + tid; idx < (part + 1) * 4096; idx += 256) {
        int k = idx >> 7, n = idx & 127;
        float val;
        if (rel) {
            int h = n >> 5, nn = n & 31;
            const float* wr = w + k * 128 + h * 32;
            const float* rr = rs + h * 1024 + nn;
            float s = 0.f;
#pragma unroll
            for (int jj = 0; jj < 32; jj++) s += wr[jj] * rr[jj * 32];
            val = s;
        } else {
            val = w[k * 128 + n];
        }
        __nv_bfloat16 h, l;
        bsplit(val, h, l);
        ih[n * WROW + k] = h;
        il[n * WROW + k] = l;
    }
    if (part == 0 && rel && jobs.bout[j] && tid < 128) {
        int h = tid >> 5, nn = tid & 31;
        const float* b = jobs.bin[j];
        float s = 0.f;
#pragma unroll
        for (int jj = 0; jj < 32; jj++) s += b[h * 32 + jj] * rs[h * 1024 + jj * 32 + nn];
        jobs.bout[j][tid] = s;
    }
}

// ---------------- mma.sync GEMM (64-row tile, 256 thr, 2 CTA/SM) -------------
#define EPI_NONE 0
#define EPI_RELU 1
#define EPI_GATED 2

#define SM_A 0
#define SM_W (2 * AIMG_BYTES)              // 34816
#define SMEM_MM (2 * AIMG_BYTES + 2 * WIMG_BYTES)   // 104448

template <bool NORM, int EPI>
__global__ void __launch_bounds__(256, 2)
mm_mma_kernel(const float* __restrict__ A, const __nv_bfloat16* __restrict__ Wimg,
              const float* __restrict__ bias, float* __restrict__ C, int N,
              const float* __restrict__ gate_p, const float* __restrict__ xprev,
              const float* __restrict__ den) {
    extern __shared__ char smem[];
    int tid = threadIdx.x;
    int wid = tid >> 5;
    int lane = tid & 31;
    int row0 = blockIdx.x * 64;
    uint32_t sb = smem_u32(smem);

    // async-copy pre-packed W hi+lo (69632 B) while we convert A
#pragma unroll
    for (int j = 0; j < 17; j++) {
        int i = tid + j * 256;
        if (i < 4352) cp_async16(sb + SM_W + i * 16, (const float4*)Wimg + i);
    }
    asm volatile("cp.async.commit_group;" ::: "memory");

    // convert A tile (64 rows) -> bf16 hi/lo, [r][k] stride 136
#pragma unroll
    for (int it = 0; it < 8; ++it) {
        int i = tid + it * 256;
        int r = i >> 5;
        int k = (i & 31) * 4;
        float4 av = make_float4(0.f, 0.f, 0.f, 0.f);
        int row = row0 + r;
        if (row < N) av = *(const float4*)(A + (size_t)row * HC + k);
        if (NORM) {
            float rcp = 1.f / fmaxf(den[(size_t)row * 4 + (k >> 5)], 1e-37f);
            av.x = gelu_exact(av.x * rcp); av.y = gelu_exact(av.y * rcp);
            av.z = gelu_exact(av.z * rcp); av.w = gelu_exact(av.w * rcp);
        }
        __nv_bfloat162 h01 = __float22bfloat162_rn(make_float2(av.x, av.y));
        __nv_bfloat162 h23 = __float22bfloat162_rn(make_float2(av.z, av.w));
        float2 f01 = __bfloat1622float2(h01);
        float2 f23 = __bfloat1622float2(h23);
        __nv_bfloat162 l01 = __float22bfloat162_rn(make_float2(av.x - f01.x, av.y - f01.y));
        __nv_bfloat162 l23 = __float22bfloat162_rn(make_float2(av.z - f23.x, av.w - f23.y));
        uint32_t off = (uint32_t)(r * WROW + k) * 2;
        *(uint2*)(smem + SM_A + off) = make_uint2(*(uint32_t*)&h01, *(uint32_t*)&h23);
        *(uint2*)(smem + SM_A + AIMG_BYTES + off) = make_uint2(*(uint32_t*)&l01, *(uint32_t*)&l23);
    }
    asm volatile("cp.async.wait_group 0;" ::: "memory");
    __syncthreads();

    int warpM = wid >> 2;           // 0..1 -> 32 rows
    int warpN = wid & 3;            // 0..3 -> 32 cols
    uint32_t a_lane = sb + SM_A +
        ((uint32_t)((warpM * 32 + (lane & 15)) * WROW + ((lane >> 4) << 3)) << 1);
    uint32_t b_lane = sb + SM_W +
        ((uint32_t)((warpN * 32 + (lane & 7) + ((lane >> 4) << 3)) * WROW +
                    (((lane >> 3) & 1) << 3)) << 1);

    float acc[2][4][4];
#pragma unroll
    for (int i = 0; i < 2; i++)
#pragma unroll
        for (int j = 0; j < 4; j++)
#pragma unroll
            for (int q = 0; q < 4; q++) acc[i][j][q] = 0.f;

#pragma unroll
    for (int p = 0; p < 3; p++) {
        uint32_t abase = a_lane + (p == 2 ? (uint32_t)AIMG_BYTES : 0u);
        uint32_t bbase = b_lane + (p == 1 ? (uint32_t)WIMG_BYTES : 0u);
#pragma unroll
        for (int ks = 0; ks < 8; ks++) {
            uint32_t ar[2][4], br[2][4];
            ldm_x4(ar[0], abase + ks * 32);
            ldm_x4(ar[1], abase + ks * 32 + 16 * WROW * 2);
            ldm_x4(br[0], bbase + ks * 32);
            ldm_x4(br[1], bbase + ks * 32 + 16 * WROW * 2);
#pragma unroll
            for (int mt = 0; mt < 2; mt++) {
                mma16816(acc[mt][0], ar[mt], br[0] + 0);
                mma16816(acc[mt][1], ar[mt], br[0] + 2);
                mma16816(acc[mt][2], ar[mt], br[1] + 0);
                mma16816(acc[mt][3], ar[mt], br[1] + 2);
            }
        }
    }

    // epilogue
    int gid = lane >> 2, tq = lane & 3;
    float g = 0.f, og = 0.f;
    if (EPI == EPI_GATED) { g = 1.f / (1.f + expf(-*gate_p)); og = 1.f - g; }
#pragma unroll
    for (int mt = 0; mt < 2; mt++) {
#pragma unroll
        for (int nt = 0; nt < 4; nt++) {
            int col = warpN * 32 + nt * 8 + tq * 2;
            float2 bv = *(const float2*)(bias + col);
#pragma unroll
            for (int half = 0; half < 2; half++) {
                int row = row0 + warpM * 32 + mt * 16 + gid + half * 8;
                if (row >= N) continue;
                float c0 = acc[mt][nt][half * 2 + 0] + bv.x;
                float c1 = acc[mt][nt][half * 2 + 1] + bv.y;
                if (EPI == EPI_RELU) { c0 = fmaxf(c0, 0.f); c1 = fmaxf(c1, 0.f); }
                if (EPI == EPI_GATED) {
                    float2 xp = *(const float2*)(xprev + (size_t)row * HC + col);
                    c0 = g * c0 + og * xp.x;
                    c1 = g * c1 + og * xp.y;
                }
                *(float2*)(C + (size_t)row * HC + col) = make_float2(c0, c1);
            }
        }
    }
}

// ---------------- small utility kernels ----------------
__global__ void fill_kernel(float* __restrict__ p, float v, int n) {
    int i = blockIdx.x * blockDim.x + threadIdx.x;
    if (i < n) p[i] = v;
}

// clears both dst types' den/agg in one launch
__global__ void attn_clear_kernel(float* dv, float* gv, int Nv,
                                  float* dc, float* gc, int Nc) {
    int i = blockIdx.x * blockDim.x + threadIdx.x;
    if (i < Nv * 4) dv[i] = 0.f;
    if (i < Nc * 4) dc[i] = 0.f;
    if (i < Nv * HC) gv[i] = 0.f;
    if (i < Nc * HC) gc[i] = 0.f;
}

// ---------------- attention (no amax; exp fused into alpha pass) ------------
struct AttnP {
    const float* q[2];
    const float* kt[2];
    const float* vt[2];
    const int* src[2];
    const int* dst[2];
    const float* prel[2];
    float* alpha[2];
    float* den[2];
    float* agg[2];
    int E0, Etot;
};

// warp per edge: ex[e,h] = exp(dot(q,k)*prel/sqrt(D)); den[dst] += ex (float4)
__global__ void attn_alpha_kernel(AttnP P) {
    int e = blockIdx.x * 8 + (threadIdx.x >> 5);
    if (e >= P.Etot) return;                 // warp-uniform exit
    int seg = e >= P.E0;
    int el = e - (seg ? P.E0 : 0);
    int lane = threadIdx.x & 31;
    int s = P.src[seg][el], d = P.dst[seg][el];
    float4 qv = *(const float4*)(P.q[seg] + (size_t)d * HC + lane * 4);
    float4 kv = *(const float4*)(P.kt[seg] + (size_t)s * HC + lane * 4);
    float p = qv.x * kv.x + qv.y * kv.y + qv.z * kv.z + qv.w * kv.w;
    p += __shfl_xor_sync(0xffffffffu, p, 1);
    p += __shfl_xor_sync(0xffffffffu, p, 2);
    p += __shfl_xor_sync(0xffffffffu, p, 4);
    // hoisted: all lanes participate (head sums live at lanes 0,8,16,24)
    float p1 = __shfl_sync(0xffffffffu, p, 8);
    float p2 = __shfl_sync(0xffffffffu, p, 16);
    float p3 = __shfl_sync(0xffffffffu, p, 24);
    if (lane == 0) {
        float4 pr = *(const float4*)P.prel[seg];
        float4 ex;
        ex.x = expf(p * pr.x * 0.17677669529663687f);
        ex.y = expf(p1 * pr.y * 0.17677669529663687f);
        ex.z = expf(p2 * pr.z * 0.17677669529663687f);
        ex.w = expf(p3 * pr.w * 0.17677669529663687f);
        *(float4*)(P.alpha[seg] + (size_t)el * 4) = ex;
        atomicAdd((float4*)(P.den[seg] + (size_t)d * 4), ex);
    }
}

// warp per edge: agg[dst] += vt[src] * ex (normalization fused into gated GEMM)
__global__ void attn_scatter_kernel(AttnP P) {
    int e = blockIdx.x * 8 + (threadIdx.x >> 5);
    if (e >= P.Etot) return;
    int seg = e >= P.E0;
    int el = e - (seg ? P.E0 : 0);
    int lane = threadIdx.x & 31;
    int s = P.src[seg][el], d = P.dst[seg][el];
    int h = lane >> 3;
    float w = P.alpha[seg][(size_t)el * 4 + h];
    float4 vv = *(const float4*)(P.vt[seg] + (size_t)s * HC + lane * 4);
    vv.x *= w; vv.y *= w; vv.z *= w; vv.w *= w;
    atomicAdd((float4*)(P.agg[seg] + (size_t)d * HC + lane * 4), vv);
}

// ---------------- output head ----------------
__global__ void out_head_kernel(const float* __restrict__ X, const float* __restrict__ W2,
                                const float* __restrict__ b2, const int* __restrict__ batch,
                                float* __restrict__ gsum, float* __restrict__ gcnt, int N) {
    int n = blockIdx.x * 8 + (threadIdx.x >> 5);
    if (n >= N) return;
    int lane = threadIdx.x & 31;
    float4 x = *(const float4*)(X + (size_t)n * HC + lane * 4);
    float4 wa = *(const float4*)(W2 + lane * 8);
    float4 wb = *(const float4*)(W2 + lane * 8 + 4);
    float p0 = x.x * wa.x + x.y * wa.z + x.z * wb.x + x.w * wb.z;
    float p1 = x.x * wa.y + x.y * wa.w + x.z * wb.y + x.w * wb.w;
#pragma unroll
    for (int off = 16; off > 0; off >>= 1) {
        p0 += __shfl_xor_sync(0xffffffffu, p0, off);
        p1 += __shfl_xor_sync(0xffffffffu, p1, off);
    }
    if (lane == 0) {
        float l0 = p0 + b2[0], l1 = p1 + b2[1];
        float m = fmaxf(l0, l1);
        float e0 = expf(l0 - m), e1 = expf(l1 - m);
        float inv = 1.f / (e0 + e1);
        int g = batch[n];
        atomicAdd(&gsum[g * 2 + 0], e0 * inv);
        atomicAdd(&gsum[g * 2 + 1], e1 * inv);
        atomicAdd(&gcnt[g], 1.f);
    }
}

__global__ void finalize_kernel(const float* __restrict__ gsum, const float* __restrict__ gcnt,
                                float* __restrict__ out, int G) {
    int g = blockIdx.x * blockDim.x + threadIdx.x;
    if (g >= G) return;
    float c = fmaxf(gcnt[g], 1.f);
    out[g * 2 + 0] = gsum[g * 2 + 0] / c;
    out[g * 2 + 1] = gsum[g * 2 + 1] / c;
}

// ---------------- host orchestration ----------------
static inline void fillf(float* p, float v, int n) {
    fill_kernel<<<(n + 255) / 256, 256>>>(p, v, n);
}

#define IMG(j) (wimg + (size_t)(j) * 2 * WIMG_ELEMS)
#define MMTC(NORM, EPI, A, J, B, C, N, GATE, XP, DEN)                                  \
    mm_mma_kernel<NORM, EPI><<<((N) + 63) / 64, 256, SMEM_MM>>>(A, IMG(J), B, C, N, GATE, XP, DEN)

extern "C" void kernel_launch(void* const* d_in, const int* in_sizes, int n_in,
                              void* d_out, int out_size) {
    const float* x_var = (const float*)d_in[0];
    const float* x_con = (const float*)d_in[1];
    const float* mlp_in_w = (const float*)d_in[2];
    const float* mlp_in_b = (const float*)d_in[3];
    const float* w0 = (const float*)d_in[4];
    const float* b0 = (const float*)d_in[5];
    const float* w1 = (const float*)d_in[6];
    const float* b1 = (const float*)d_in[7];
    const float* w2 = (const float*)d_in[8];
    const float* b2 = (const float*)d_in[9];
    const float* k_w = (const float*)d_in[10];
    const float* k_b = (const float*)d_in[11];
    const float* q_w = (const float*)d_in[12];
    const float* q_b = (const float*)d_in[13];
    const float* v_w = (const float*)d_in[14];
    const float* v_b = (const float*)d_in[15];
    const float* a_w = (const float*)d_in[16];
    const float* a_b = (const float*)d_in[17];
    const float* skip = (const float*)d_in[18];
    const float* a_rel = (const float*)d_in[19];
    const float* m_rel = (const float*)d_in[20];
    const float* p_rel = (const float*)d_in[21];
    const int* evc = (const int*)d_in[22];
    const int* ecv = (const int*)d_in[23];
    const int* batch = (const int*)d_in[24];
    float* out = (float*)d_out;

    int Nv = in_sizes[0] / HC;
    int Nc = in_sizes[1] / HC;
    int Evc = in_sizes[22] / 2;
    int Ecv = in_sizes[23] / 2;

    float *xs0, *xs1, *tmp, *kt0, *vt0, *kt1, *vt1, *qe0, *qe1, *aggv, *aggc;
    float *alpha, *denv, *denc, *bcomp, *gsum, *gcnt;
    __nv_bfloat16* wimg;
    cudaGetSymbolAddress((void**)&xs0, g_xs0);
    cudaGetSymbolAddress((void**)&xs1, g_xs1);
    cudaGetSymbolAddress((void**)&tmp, g_tmp);
    cudaGetSymbolAddress((void**)&kt0, g_kt0);
    cudaGetSymbolAddress((void**)&vt0, g_vt0);
    cudaGetSymbolAddress((void**)&kt1, g_kt1);
    cudaGetSymbolAddress((void**)&vt1, g_vt1);
    cudaGetSymbolAddress((void**)&qe0, g_qe0);
    cudaGetSymbolAddress((void**)&qe1, g_qe1);
    cudaGetSymbolAddress((void**)&aggv, g_aggv);
    cudaGetSymbolAddress((void**)&aggc, g_aggc);
    cudaGetSymbolAddress((void**)&alpha, g_alpha);
    cudaGetSymbolAddress((void**)&denv, g_denv);
    cudaGetSymbolAddress((void**)&denc, g_denc);
    cudaGetSymbolAddress((void**)&wimg, g_wimg);
    cudaGetSymbolAddress((void**)&bcomp, g_bcomp);
    cudaGetSymbolAddress((void**)&gsum, g_gsum);
    cudaGetSymbolAddress((void**)&gcnt, g_gcnt);

    cudaFuncSetAttribute(mm_mma_kernel<false, EPI_NONE>,
                         cudaFuncAttributeMaxDynamicSharedMemorySize, SMEM_MM);
    cudaFuncSetAttribute(mm_mma_kernel<false, EPI_RELU>,
                         cudaFuncAttributeMaxDynamicSharedMemorySize, SMEM_MM);
    cudaFuncSetAttribute(mm_mma_kernel<true, EPI_GATED>,
                         cudaFuncAttributeMaxDynamicSharedMemorySize, SMEM_MM);

    // ---- weight packing ----
    PackJobs pj;
    for (int j = 0; j < NW; j++) { pj.w[j] = nullptr; pj.rel[j] = nullptr; pj.bin[j] = nullptr; pj.bout[j] = nullptr; }
    for (int t = 0; t < 2; t++)
        for (int i = 0; i < 3; i++) pj.w[t * 3 + i] = mlp_in_w + (size_t)(t * 3 + i) * 16384;
    for (int li = 0; li < 4; li++) {
        pj.w[6 + li] = k_w + (size_t)li * 16384;
        pj.rel[6 + li] = a_rel + (size_t)li * 4096;
        pj.bin[6 + li] = k_b + (size_t)li * 128;
        pj.bout[6 + li] = bcomp + (size_t)li * 128;
        pj.w[10 + li] = v_w + (size_t)li * 16384;
        pj.rel[10 + li] = m_rel + (size_t)li * 4096;
        pj.bin[10 + li] = v_b + (size_t)li * 128;
        pj.bout[10 + li] = bcomp + (size_t)(4 + li) * 128;
        pj.w[14 + li] = q_w + (size_t)li * 16384;
        pj.w[18 + li] = a_w + (size_t)li * 16384;
    }
    pj.w[22] = w0;
    pj.w[23] = w1;
    pack_kernel<<<dim3(NW, 4), 256>>>(pj, wimg);

    // ---- input MLPs ----
    MMTC(false, EPI_RELU, x_var, 0, mlp_in_b + 0 * 128, xs0, Nv, nullptr, nullptr, nullptr);
    MMTC(false, EPI_RELU, xs0,   1, mlp_in_b + 1 * 128, xs0, Nv, nullptr, nullptr, nullptr);
    MMTC(false, EPI_NONE, xs0,   2, mlp_in_b + 2 * 128, xs0, Nv, nullptr, nullptr, nullptr);
    MMTC(false, EPI_RELU, x_con, 3, mlp_in_b + 3 * 128, xs1, Nc, nullptr, nullptr, nullptr);
    MMTC(false, EPI_RELU, xs1,   4, mlp_in_b + 4 * 128, xs1, Nc, nullptr, nullptr, nullptr);
    MMTC(false, EPI_NONE, xs1,   5, mlp_in_b + 5 * 128, xs1, Nc, nullptr, nullptr, nullptr);

    // ---- HGTConv layers ----
    for (int l = 0; l < LAYERS; l++) {
        int li0 = l * 2 + 0, li1 = l * 2 + 1;

        // projections (6 GEMMs, separate launches — proven granularity)
        MMTC(false, EPI_NONE, xs0, 6 + li0,  bcomp + (size_t)li0 * 128,       kt0, Nv, nullptr, nullptr, nullptr);
        MMTC(false, EPI_NONE, xs0, 10 + li0, bcomp + (size_t)(4 + li0) * 128, vt0, Nv, nullptr, nullptr, nullptr);
        MMTC(false, EPI_NONE, xs1, 6 + li1,  bcomp + (size_t)li1 * 128,       kt1, Nc, nullptr, nullptr, nullptr);
        MMTC(false, EPI_NONE, xs1, 10 + li1, bcomp + (size_t)(4 + li1) * 128, vt1, Nc, nullptr, nullptr, nullptr);
        MMTC(false, EPI_NONE, xs1, 14 + li1, q_b + (size_t)li1 * 128,         qe0, Nc, nullptr, nullptr, nullptr);
        MMTC(false, EPI_NONE, xs0, 14 + li0, q_b + (size_t)li0 * 128,         qe1, Nv, nullptr, nullptr, nullptr);

        // clear den/agg for both dst types
        {
            int mx = (Nv > Nc ? Nv : Nc) * HC;
            attn_clear_kernel<<<(mx + 255) / 256, 256>>>(denv, aggv, Nv, denc, aggc, Nc);
        }

        // fused attention (both edge types per launch; no amax)
        AttnP ap{};
        ap.q[0] = qe0; ap.kt[0] = kt0; ap.vt[0] = vt0;
        ap.src[0] = evc; ap.dst[0] = evc + Evc;
        ap.prel[0] = p_rel + (size_t)li0 * 4;
        ap.alpha[0] = alpha; ap.den[0] = denc; ap.agg[0] = aggc;
        ap.q[1] = qe1; ap.kt[1] = kt1; ap.vt[1] = vt1;
        ap.src[1] = ecv; ap.dst[1] = ecv + Ecv;
        ap.prel[1] = p_rel + (size_t)li1 * 4;
        ap.alpha[1] = alpha + (size_t)Evc * 4; ap.den[1] = denv; ap.agg[1] = aggv;
        ap.E0 = Evc; ap.Etot = Evc + Ecv;
        attn_alpha_kernel<<<(ap.Etot + 7) / 8, 256>>>(ap);
        attn_scatter_kernel<<<(ap.Etot + 7) / 8, 256>>>(ap);

        // gated update
        MMTC(true, EPI_GATED, aggv, 18 + li0, a_b + (size_t)li0 * 128,
             xs0, Nv, skip + li0, xs0, denv);
        MMTC(true, EPI_GATED, aggc, 18 + li1, a_b + (size_t)li1 * 128,
             xs1, Nc, skip + li1, xs1, denc);
    }

    // ---- output head ----
    MMTC(false, EPI_RELU, xs0, 22, b0, tmp, Nv, nullptr, nullptr, nullptr);
    MMTC(false, EPI_RELU, tmp, 23, b1, tmp, Nv, nullptr, nullptr, nullptr);
    fillf(gsum, 0.f, NG * 2);
    fillf(gcnt, 0.f, NG);
    out_head_kernel<<<(Nv + 7) / 8, 256>>>(tmp, w2, b2, batch, gsum, gcnt, Nv);
    finalize_kernel<<<(NG + 255) / 256, 256>>>(gsum, gcnt, out, NG);
}

// round 8
// speedup vs baseline: 1.2223x; 1.0647x over previous
#include <cuda_runtime.h>
#include <cuda_bf16.h>
#include <math.h>
#include <stdint.h>

#define HC 128
#define NVMAX 50000
#define NEMAX 400000
#define NG 512
#define LAYERS 2
#define NW 24

// packed weight image: [n][k] bf16, row stride 136 (pad 8), hi then lo
#define WROW 136
#define WIMG_ELEMS (128 * WROW)            // 17408 bf16 per (hi|lo) image
#define WIMG_BYTES (WIMG_ELEMS * 2)        // 34816 B
#define AIMG_BYTES (64 * WROW * 2)         // 17408 B per (hi|lo), 64-row tile

// ---------------- scratch (device globals; no allocation) ----------------
__device__ float g_xs0[NVMAX * HC];
__device__ float g_xs1[NVMAX * HC];
__device__ float g_tmp[NVMAX * HC];
__device__ float g_kt0[NVMAX * HC];
__device__ float g_vt0[NVMAX * HC];
__device__ float g_kt1[NVMAX * HC];
__device__ float g_vt1[NVMAX * HC];
__device__ float g_qe0[NVMAX * HC];   // Q of con nodes (dst of et=0)
__device__ float g_qe1[NVMAX * HC];   // Q of var nodes (dst of et=1)
__device__ float g_aggv[NVMAX * HC];
__device__ float g_aggc[NVMAX * HC];
__device__ float g_denv[NVMAX * 4];
__device__ float g_denc[NVMAX * 4];
__device__ __align__(16) __nv_bfloat16 g_wimg[NW * 2 * WIMG_ELEMS];
__device__ float g_bcomp[8 * HC];
__device__ float g_gsum[NG * 2];
__device__ float g_gcnt[NG];

// ---------------- helpers ----------------
__device__ __forceinline__ uint32_t smem_u32(const void* p) {
    uint32_t a;
    asm("{ .reg .u64 t; cvta.to.shared.u64 t, %1; cvt.u32.u64 %0, t; }" : "=r"(a) : "l"(p));
    return a;
}
__device__ __forceinline__ void bsplit(float x, __nv_bfloat16& h, __nv_bfloat16& l) {
    h = __float2bfloat16(x);
    l = __float2bfloat16(x - __bfloat162float(h));
}
__device__ __forceinline__ float gelu_exact(float x) {
    return 0.5f * x * (1.f + erff(x * 0.70710678118654752440f));
}
__device__ __forceinline__ void ldm_x4(uint32_t* r, uint32_t addr) {
    asm volatile("ldmatrix.sync.aligned.m8n8.x4.shared.b16 {%0,%1,%2,%3}, [%4];"
                 : "=r"(r[0]), "=r"(r[1]), "=r"(r[2]), "=r"(r[3]) : "r"(addr));
}
__device__ __forceinline__ void mma16816(float* c, const uint32_t* a, const uint32_t* b) {
    asm volatile("mma.sync.aligned.m16n8k16.row.col.f32.bf16.bf16.f32 "
                 "{%0,%1,%2,%3}, {%4,%5,%6,%7}, {%8,%9}, {%0,%1,%2,%3};"
                 : "+f"(c[0]), "+f"(c[1]), "+f"(c[2]), "+f"(c[3])
                 : "r"(a[0]), "r"(a[1]), "r"(a[2]), "r"(a[3]), "r"(b[0]), "r"(b[1]));
}
__device__ __forceinline__ void cp_async16(uint32_t saddr, const void* gaddr) {
    asm volatile("cp.async.cg.shared.global [%0], [%1], 16;" :: "r"(saddr), "l"(gaddr));
}

// ---------------- weight pre-pack (compose + split, [n][k] stride-136) ------
struct PackJobs {
    const float* w[NW];
    const float* rel[NW];
    const float* bin[NW];
    float* bout[NW];
};

__global__ void pack_kernel(PackJobs jobs, __nv_bfloat16* img) {
    int j = blockIdx.x;
    int part = blockIdx.y;
    int tid = threadIdx.x;
    const float* w = jobs.w[j];
    const float* rel = jobs.rel[j];
    __shared__ float rs[4096];
    if (rel) {
        for (int i = tid; i < 4096; i += 256) rs[i] = rel[i];
        __syncthreads();
    }
    __nv_bfloat16* ih = img + (size_t)j * 2 * WIMG_ELEMS;
    __nv_bfloat16* il = ih + WIMG_ELEMS;
    for (int idx = part * 4096 + tid; idx < (part + 1) * 4096; idx += 256) {
        int k = idx >> 7, n = idx & 127;
        float val;
        if (rel) {
            int h = n >> 5, nn = n & 31;
            const float* wr = w + k * 128 + h * 32;
            const float* rr = rs + h * 1024 + nn;
            float s = 0.f;
#pragma unroll
            for (int jj = 0; jj < 32; jj++) s += wr[jj] * rr[jj * 32];
            val = s;
        } else {
            val = w[k * 128 + n];
        }
        __nv_bfloat16 h, l;
        bsplit(val, h, l);
        ih[n * WROW + k] = h;
        il[n * WROW + k] = l;
    }
    if (part == 0 && rel && jobs.bout[j] && tid < 128) {
        int h = tid >> 5, nn = tid & 31;
        const float* b = jobs.bin[j];
        float s = 0.f;
#pragma unroll
        for (int jj = 0; jj < 32; jj++) s += b[h * 32 + jj] * rs[h * 1024 + jj * 32 + nn];
        jobs.bout[j][tid] = s;
    }
}

// ---------------- shared GEMM pieces ----------------
#define SM_A 0
#define SM_W (2 * AIMG_BYTES)              // 34816
#define SMEM_MM (2 * AIMG_BYTES + 2 * WIMG_BYTES)   // 104448

#define EPI_NONE 0
#define EPI_RELU 1
#define EPI_GATED 2

// convert 64-row fp32 A tile -> smem bf16 hi/lo (256 threads)
template <bool NORM>
__device__ __forceinline__ void convert_A64(const float* __restrict__ A, int row0, int N,
                                            char* smem, const float* __restrict__ den, int tid) {
#pragma unroll
    for (int it = 0; it < 8; ++it) {
        int i = tid + it * 256;
        int r = i >> 5;
        int k = (i & 31) * 4;
        float4 av = make_float4(0.f, 0.f, 0.f, 0.f);
        int row = row0 + r;
        if (row < N) av = *(const float4*)(A + (size_t)row * HC + k);
        if (NORM) {
            float rcp = 1.f / fmaxf(den[(size_t)row * 4 + (k >> 5)], 1e-37f);
            av.x = gelu_exact(av.x * rcp); av.y = gelu_exact(av.y * rcp);
            av.z = gelu_exact(av.z * rcp); av.w = gelu_exact(av.w * rcp);
        }
        __nv_bfloat162 h01 = __float22bfloat162_rn(make_float2(av.x, av.y));
        __nv_bfloat162 h23 = __float22bfloat162_rn(make_float2(av.z, av.w));
        float2 f01 = __bfloat1622float2(h01);
        float2 f23 = __bfloat1622float2(h23);
        __nv_bfloat162 l01 = __float22bfloat162_rn(make_float2(av.x - f01.x, av.y - f01.y));
        __nv_bfloat162 l23 = __float22bfloat162_rn(make_float2(av.z - f23.x, av.w - f23.y));
        uint32_t off = (uint32_t)(r * WROW + k) * 2;
        *(uint2*)(smem + SM_A + off) = make_uint2(*(uint32_t*)&h01, *(uint32_t*)&h23);
        *(uint2*)(smem + SM_A + AIMG_BYTES + off) = make_uint2(*(uint32_t*)&l01, *(uint32_t*)&l23);
    }
}

__device__ __forceinline__ void load_W_async(uint32_t sb, const __nv_bfloat16* Wimg, int tid) {
#pragma unroll
    for (int j = 0; j < 17; j++) {
        int i = tid + j * 256;
        if (i < 4352) cp_async16(sb + SM_W + i * 16, (const float4*)Wimg + i);
    }
    asm volatile("cp.async.commit_group;" ::: "memory");
}

__device__ __forceinline__ void mma_tile3(uint32_t a_lane, uint32_t b_lane, float acc[2][4][4]) {
#pragma unroll
    for (int i = 0; i < 2; i++)
#pragma unroll
        for (int j = 0; j < 4; j++)
#pragma unroll
            for (int q = 0; q < 4; q++) acc[i][j][q] = 0.f;
#pragma unroll
    for (int p = 0; p < 3; p++) {
        uint32_t abase = a_lane + (p == 2 ? (uint32_t)AIMG_BYTES : 0u);
        uint32_t bbase = b_lane + (p == 1 ? (uint32_t)WIMG_BYTES : 0u);
#pragma unroll
        for (int ks = 0; ks < 8; ks++) {
            uint32_t ar[2][4], br[2][4];
            ldm_x4(ar[0], abase + ks * 32);
            ldm_x4(ar[1], abase + ks * 32 + 16 * WROW * 2);
            ldm_x4(br[0], bbase + ks * 32);
            ldm_x4(br[1], bbase + ks * 32 + 16 * WROW * 2);
#pragma unroll
            for (int mt = 0; mt < 2; mt++) {
                mma16816(acc[mt][0], ar[mt], br[0] + 0);
                mma16816(acc[mt][1], ar[mt], br[0] + 2);
                mma16816(acc[mt][2], ar[mt], br[1] + 0);
                mma16816(acc[mt][3], ar[mt], br[1] + 2);
            }
        }
    }
}

// ---------------- chain GEMM kernel (1..3 steps, shared A tile) --------------
struct ChainP {
    const float* A;
    const __nv_bfloat16* W[3];
    const float* bias[3];
    float* Cg[3];     // non-null => write global; null => chain result into smem A
    int relu[3];
    int nsteps;
    int N;
};

__global__ void __launch_bounds__(256, 2)
chain_kernel(ChainP P) {
    extern __shared__ char smem[];
    int tid = threadIdx.x;
    int wid = tid >> 5;
    int lane = tid & 31;
    int row0 = blockIdx.x * 64;
    uint32_t sb = smem_u32(smem);

    load_W_async(sb, P.W[0], tid);
    convert_A64<false>(P.A, row0, P.N, smem, nullptr, tid);
    asm volatile("cp.async.wait_group 0;" ::: "memory");
    __syncthreads();

    int warpM = wid >> 2;
    int warpN = wid & 3;
    uint32_t a_lane = sb + SM_A +
        ((uint32_t)((warpM * 32 + (lane & 15)) * WROW + ((lane >> 4) << 3)) << 1);
    uint32_t b_lane = sb + SM_W +
        ((uint32_t)((warpN * 32 + (lane & 7) + ((lane >> 4) << 3)) * WROW +
                    (((lane >> 3) & 1) << 3)) << 1);
    int gid = lane >> 2, tq = lane & 3;

    for (int s = 0; s < P.nsteps; s++) {
        float acc[2][4][4];
        mma_tile3(a_lane, b_lane, acc);
        bool last = (s + 1 == P.nsteps);
        __syncthreads();                 // all warps done reading W (and A)
        if (!last) load_W_async(sb, P.W[s + 1], tid);

        const float* bias = P.bias[s];
        float* Cg = P.Cg[s];
        int rl = P.relu[s];
#pragma unroll
        for (int mt = 0; mt < 2; mt++) {
#pragma unroll
            for (int nt = 0; nt < 4; nt++) {
                int col = warpN * 32 + nt * 8 + tq * 2;
                float2 bv = *(const float2*)(bias + col);
#pragma unroll
                for (int half = 0; half < 2; half++) {
                    int rloc = warpM * 32 + mt * 16 + gid + half * 8;
                    float c0 = acc[mt][nt][half * 2 + 0] + bv.x;
                    float c1 = acc[mt][nt][half * 2 + 1] + bv.y;
                    if (rl) { c0 = fmaxf(c0, 0.f); c1 = fmaxf(c1, 0.f); }
                    if (Cg) {
                        int row = row0 + rloc;
                        if (row < P.N)
                            *(float2*)(Cg + (size_t)row * HC + col) = make_float2(c0, c1);
                    } else {
                        __nv_bfloat162 h2 = __float22bfloat162_rn(make_float2(c0, c1));
                        float2 hf = __bfloat1622float2(h2);
                        __nv_bfloat162 l2 =
                            __float22bfloat162_rn(make_float2(c0 - hf.x, c1 - hf.y));
                        uint32_t off = (uint32_t)(rloc * WROW + col) * 2;
                        *(uint32_t*)(smem + SM_A + off) = *(uint32_t*)&h2;
                        *(uint32_t*)(smem + SM_A + AIMG_BYTES + off) = *(uint32_t*)&l2;
                    }
                }
            }
        }
        if (!last) {
            asm volatile("cp.async.wait_group 0;" ::: "memory");
            __syncthreads();             // W[s+1] + chained A stores visible
        }
    }
}

// ---------------- gated GEMM (NORM: per-row/head den division + gelu) --------
__global__ void __launch_bounds__(256, 2)
mm_gated_kernel(const float* __restrict__ A, const __nv_bfloat16* __restrict__ Wimg,
                const float* __restrict__ bias, float* __restrict__ C, int N,
                const float* __restrict__ gate_p, const float* __restrict__ xprev,
                const float* __restrict__ den) {
    extern __shared__ char smem[];
    int tid = threadIdx.x;
    int wid = tid >> 5;
    int lane = tid & 31;
    int row0 = blockIdx.x * 64;
    uint32_t sb = smem_u32(smem);

    load_W_async(sb, Wimg, tid);
    convert_A64<true>(A, row0, N, smem, den, tid);
    asm volatile("cp.async.wait_group 0;" ::: "memory");
    __syncthreads();

    int warpM = wid >> 2;
    int warpN = wid & 3;
    uint32_t a_lane = sb + SM_A +
        ((uint32_t)((warpM * 32 + (lane & 15)) * WROW + ((lane >> 4) << 3)) << 1);
    uint32_t b_lane = sb + SM_W +
        ((uint32_t)((warpN * 32 + (lane & 7) + ((lane >> 4) << 3)) * WROW +
                    (((lane >> 3) & 1) << 3)) << 1);

    float acc[2][4][4];
    mma_tile3(a_lane, b_lane, acc);

    int gid = lane >> 2, tq = lane & 3;
    float g = 1.f / (1.f + expf(-*gate_p));
    float og = 1.f - g;
#pragma unroll
    for (int mt = 0; mt < 2; mt++) {
#pragma unroll
        for (int nt = 0; nt < 4; nt++) {
            int col = warpN * 32 + nt * 8 + tq * 2;
            float2 bv = *(const float2*)(bias + col);
#pragma unroll
            for (int half = 0; half < 2; half++) {
                int row = row0 + warpM * 32 + mt * 16 + gid + half * 8;
                if (row >= N) continue;
                float c0 = acc[mt][nt][half * 2 + 0] + bv.x;
                float c1 = acc[mt][nt][half * 2 + 1] + bv.y;
                float2 xp = *(const float2*)(xprev + (size_t)row * HC + col);
                c0 = g * c0 + og * xp.x;
                c1 = g * c1 + og * xp.y;
                *(float2*)(C + (size_t)row * HC + col) = make_float2(c0, c1);
            }
        }
    }
}

// ---------------- small utility kernels ----------------
__global__ void fill_kernel(float* __restrict__ p, float v, int n) {
    int i = blockIdx.x * blockDim.x + threadIdx.x;
    if (i < n) p[i] = v;
}

__global__ void attn_clear_kernel(float* dv, float* gv, int Nv,
                                  float* dc, float* gc, int Nc) {
    int i = blockIdx.x * blockDim.x + threadIdx.x;
    if (i < Nv * 4) dv[i] = 0.f;
    if (i < Nc * 4) dc[i] = 0.f;
    if (i < Nv * HC) gv[i] = 0.f;
    if (i < Nc * HC) gc[i] = 0.f;
}

// ---------------- fused attention (alpha+exp+scatter, one pass) --------------
struct AttnP {
    const float* q[2];
    const float* kt[2];
    const float* vt[2];
    const int* src[2];
    const int* dst[2];
    const float* prel[2];
    float* den[2];
    float* agg[2];
    int E0, Etot;
};

__global__ void attn_fused_kernel(AttnP P) {
    int e = blockIdx.x * 8 + (threadIdx.x >> 5);
    if (e >= P.Etot) return;                 // warp-uniform exit
    int seg = e >= P.E0;
    int el = e - (seg ? P.E0 : 0);
    int lane = threadIdx.x & 31;
    int s = P.src[seg][el], d = P.dst[seg][el];
    float4 qv = *(const float4*)(P.q[seg] + (size_t)d * HC + lane * 4);
    float4 kv = *(const float4*)(P.kt[seg] + (size_t)s * HC + lane * 4);
    float p = qv.x * kv.x + qv.y * kv.y + qv.z * kv.z + qv.w * kv.w;
    p += __shfl_xor_sync(0xffffffffu, p, 1);
    p += __shfl_xor_sync(0xffffffffu, p, 2);
    p += __shfl_xor_sync(0xffffffffu, p, 4);
    // head sums live at lanes 0,8,16,24; broadcast within each 8-lane group
    float ph = __shfl_sync(0xffffffffu, p, lane & 24);
    int h = lane >> 3;
    float ex = expf(ph * P.prel[seg][h] * 0.17677669529663687f);
    if ((lane & 7) == 0)
        atomicAdd(P.den[seg] + (size_t)d * 4 + h, ex);
    float4 vv = *(const float4*)(P.vt[seg] + (size_t)s * HC + lane * 4);
    vv.x *= ex; vv.y *= ex; vv.z *= ex; vv.w *= ex;
    atomicAdd((float4*)(P.agg[seg] + (size_t)d * HC + lane * 4), vv);
}

// ---------------- output head ----------------
__global__ void out_head_kernel(const float* __restrict__ X, const float* __restrict__ W2,
                                const float* __restrict__ b2, const int* __restrict__ batch,
                                float* __restrict__ gsum, float* __restrict__ gcnt, int N) {
    int n = blockIdx.x * 8 + (threadIdx.x >> 5);
    if (n >= N) return;
    int lane = threadIdx.x & 31;
    float4 x = *(const float4*)(X + (size_t)n * HC + lane * 4);
    float4 wa = *(const float4*)(W2 + lane * 8);
    float4 wb = *(const float4*)(W2 + lane * 8 + 4);
    float p0 = x.x * wa.x + x.y * wa.z + x.z * wb.x + x.w * wb.z;
    float p1 = x.x * wa.y + x.y * wa.w + x.z * wb.y + x.w * wb.w;
#pragma unroll
    for (int off = 16; off > 0; off >>= 1) {
        p0 += __shfl_xor_sync(0xffffffffu, p0, off);
        p1 += __shfl_xor_sync(0xffffffffu, p1, off);
    }
    if (lane == 0) {
        float l0 = p0 + b2[0], l1 = p1 + b2[1];
        float m = fmaxf(l0, l1);
        float e0 = expf(l0 - m), e1 = expf(l1 - m);
        float inv = 1.f / (e0 + e1);
        int g = batch[n];
        atomicAdd(&gsum[g * 2 + 0], e0 * inv);
        atomicAdd(&gsum[g * 2 + 1], e1 * inv);
        atomicAdd(&gcnt[g], 1.f);
    }
}

__global__ void finalize_kernel(const float* __restrict__ gsum, const float* __restrict__ gcnt,
                                float* __restrict__ out, int G) {
    int g = blockIdx.x * blockDim.x + threadIdx.x;
    if (g >= G) return;
    float c = fmaxf(gcnt[g], 1.f);
    out[g * 2 + 0] = gsum[g * 2 + 0] / c;
    out[g * 2 + 1] = gsum[g * 2 + 1] / c;
}

// ---------------- host orchestration ----------------
static inline void fillf(float* p, float v, int n) {
    fill_kernel<<<(n + 255) / 256, 256>>>(p, v, n);
}

extern "C" void kernel_launch(void* const* d_in, const int* in_sizes, int n_in,
                              void* d_out, int out_size) {
    const float* x_var = (const float*)d_in[0];
    const float* x_con = (const float*)d_in[1];
    const float* mlp_in_w = (const float*)d_in[2];
    const float* mlp_in_b = (const float*)d_in[3];
    const float* w0 = (const float*)d_in[4];
    const float* b0 = (const float*)d_in[5];
    const float* w1 = (const float*)d_in[6];
    const float* b1 = (const float*)d_in[7];
    const float* w2 = (const float*)d_in[8];
    const float* b2 = (const float*)d_in[9];
    const float* k_w = (const float*)d_in[10];
    const float* k_b = (const float*)d_in[11];
    const float* q_w = (const float*)d_in[12];
    const float* q_b = (const float*)d_in[13];
    const float* v_w = (const float*)d_in[14];
    const float* v_b = (const float*)d_in[15];
    const float* a_w = (const float*)d_in[16];
    const float* a_b = (const float*)d_in[17];
    const float* skip = (const float*)d_in[18];
    const float* a_rel = (const float*)d_in[19];
    const float* m_rel = (const float*)d_in[20];
    const float* p_rel = (const float*)d_in[21];
    const int* evc = (const int*)d_in[22];
    const int* ecv = (const int*)d_in[23];
    const int* batch = (const int*)d_in[24];
    float* out = (float*)d_out;

    int Nv = in_sizes[0] / HC;
    int Nc = in_sizes[1] / HC;
    int Evc = in_sizes[22] / 2;
    int Ecv = in_sizes[23] / 2;

    float *xs0, *xs1, *tmp, *kt0, *vt0, *kt1, *vt1, *qe0, *qe1, *aggv, *aggc;
    float *denv, *denc, *bcomp, *gsum, *gcnt;
    __nv_bfloat16* wimg;
    cudaGetSymbolAddress((void**)&xs0, g_xs0);
    cudaGetSymbolAddress((void**)&xs1, g_xs1);
    cudaGetSymbolAddress((void**)&tmp, g_tmp);
    cudaGetSymbolAddress((void**)&kt0, g_kt0);
    cudaGetSymbolAddress((void**)&vt0, g_vt0);
    cudaGetSymbolAddress((void**)&kt1, g_kt1);
    cudaGetSymbolAddress((void**)&vt1, g_vt1);
    cudaGetSymbolAddress((void**)&qe0, g_qe0);
    cudaGetSymbolAddress((void**)&qe1, g_qe1);
    cudaGetSymbolAddress((void**)&aggv, g_aggv);
    cudaGetSymbolAddress((void**)&aggc, g_aggc);
    cudaGetSymbolAddress((void**)&denv, g_denv);
    cudaGetSymbolAddress((void**)&denc, g_denc);
    cudaGetSymbolAddress((void**)&wimg, g_wimg);
    cudaGetSymbolAddress((void**)&bcomp, g_bcomp);
    cudaGetSymbolAddress((void**)&gsum, g_gsum);
    cudaGetSymbolAddress((void**)&gcnt, g_gcnt);

    cudaFuncSetAttribute(chain_kernel, cudaFuncAttributeMaxDynamicSharedMemorySize, SMEM_MM);
    cudaFuncSetAttribute(mm_gated_kernel, cudaFuncAttributeMaxDynamicSharedMemorySize, SMEM_MM);

    // ---- weight packing ----
    PackJobs pj;
    for (int j = 0; j < NW; j++) { pj.w[j] = nullptr; pj.rel[j] = nullptr; pj.bin[j] = nullptr; pj.bout[j] = nullptr; }
    for (int t = 0; t < 2; t++)
        for (int i = 0; i < 3; i++) pj.w[t * 3 + i] = mlp_in_w + (size_t)(t * 3 + i) * 16384;
    for (int li = 0; li < 4; li++) {
        pj.w[6 + li] = k_w + (size_t)li * 16384;
        pj.rel[6 + li] = a_rel + (size_t)li * 4096;
        pj.bin[6 + li] = k_b + (size_t)li * 128;
        pj.bout[6 + li] = bcomp + (size_t)li * 128;
        pj.w[10 + li] = v_w + (size_t)li * 16384;
        pj.rel[10 + li] = m_rel + (size_t)li * 4096;
        pj.bin[10 + li] = v_b + (size_t)li * 128;
        pj.bout[10 + li] = bcomp + (size_t)(4 + li) * 128;
        pj.w[14 + li] = q_w + (size_t)li * 16384;
        pj.w[18 + li] = a_w + (size_t)li * 16384;
    }
    pj.w[22] = w0;
    pj.w[23] = w1;
    pack_kernel<<<dim3(NW, 4), 256>>>(pj, wimg);

#define IMG(j) (wimg + (size_t)(j) * 2 * WIMG_ELEMS)

    // ---- input MLPs: one 3-step chain per node type ----
    for (int t = 0; t < 2; t++) {
        ChainP c{};
        c.A = (t == 0) ? x_var : x_con;
        c.N = (t == 0) ? Nv : Nc;
        c.nsteps = 3;
        for (int i = 0; i < 3; i++) {
            c.W[i] = IMG(t * 3 + i);
            c.bias[i] = mlp_in_b + (size_t)(t * 3 + i) * 128;
            c.Cg[i] = nullptr;
            c.relu[i] = (i < 2);
        }
        c.Cg[2] = (t == 0) ? xs0 : xs1;
        chain_kernel<<<(c.N + 63) / 64, 256, SMEM_MM>>>(c);
    }

    // ---- HGTConv layers ----
    for (int l = 0; l < LAYERS; l++) {
        int li0 = l * 2 + 0, li1 = l * 2 + 1;

        // K+V chain per source type (shared A-convert), Q single chains
        for (int t = 0; t < 2; t++) {
            int li = (t == 0) ? li0 : li1;
            ChainP c{};
            c.A = (t == 0) ? xs0 : xs1;
            c.N = (t == 0) ? Nv : Nc;
            c.nsteps = 2;
            c.W[0] = IMG(6 + li);  c.bias[0] = bcomp + (size_t)li * 128;
            c.Cg[0] = (t == 0) ? kt0 : kt1;  c.relu[0] = 0;
            c.W[1] = IMG(10 + li); c.bias[1] = bcomp + (size_t)(4 + li) * 128;
            c.Cg[1] = (t == 0) ? vt0 : vt1;  c.relu[1] = 0;
            chain_kernel<<<(c.N + 63) / 64, 256, SMEM_MM>>>(c);
        }
        {   // Q for dst type con (uses q_w of type 1) and var (type 0)
            ChainP c{};
            c.A = xs1; c.N = Nc; c.nsteps = 1;
            c.W[0] = IMG(14 + li1); c.bias[0] = q_b + (size_t)li1 * 128;
            c.Cg[0] = qe0; c.relu[0] = 0;
            chain_kernel<<<(Nc + 63) / 64, 256, SMEM_MM>>>(c);
        }
        {
            ChainP c{};
            c.A = xs0; c.N = Nv; c.nsteps = 1;
            c.W[0] = IMG(14 + li0); c.bias[0] = q_b + (size_t)li0 * 128;
            c.Cg[0] = qe1; c.relu[0] = 0;
            chain_kernel<<<(Nv + 63) / 64, 256, SMEM_MM>>>(c);
        }

        // clear den/agg for both dst types
        {
            int mx = (Nv > Nc ? Nv : Nc) * HC;
            attn_clear_kernel<<<(mx + 255) / 256, 256>>>(denv, aggv, Nv, denc, aggc, Nc);
        }

        // fused single-pass attention (both edge types)
        AttnP ap{};
        ap.q[0] = qe0; ap.kt[0] = kt0; ap.vt[0] = vt0;
        ap.src[0] = evc; ap.dst[0] = evc + Evc;
        ap.prel[0] = p_rel + (size_t)li0 * 4;
        ap.den[0] = denc; ap.agg[0] = aggc;
        ap.q[1] = qe1; ap.kt[1] = kt1; ap.vt[1] = vt1;
        ap.src[1] = ecv; ap.dst[1] = ecv + Ecv;
        ap.prel[1] = p_rel + (size_t)li1 * 4;
        ap.den[1] = denv; ap.agg[1] = aggv;
        ap.E0 = Evc; ap.Etot = Evc + Ecv;
        attn_fused_kernel<<<(ap.Etot + 7) / 8, 256>>>(ap);

        // gated update
        mm_gated_kernel<<<(Nv + 63) / 64, 256, SMEM_MM>>>(
            aggv, IMG(18 + li0), a_b + (size_t)li0 * 128, xs0, Nv, skip + li0, xs0, denv);
        mm_gated_kernel<<<(Nc + 63) / 64, 256, SMEM_MM>>>(
            aggc, IMG(18 + li1), a_b + (size_t)li1 * 128, xs1, Nc, skip + li1, xs1, denc);
    }

    // ---- output head: 2-step chain then head reduce ----
    {
        ChainP c{};
        c.A = xs0; c.N = Nv; c.nsteps = 2;
        c.W[0] = IMG(22); c.bias[0] = b0; c.Cg[0] = nullptr; c.relu[0] = 1;
        c.W[1] = IMG(23); c.bias[1] = b1; c.Cg[1] = tmp; c.relu[1] = 1;
        chain_kernel<<<(Nv + 63) / 64, 256, SMEM_MM>>>(c);
    }
    fillf(gsum, 0.f, NG * 2);
    fillf(gcnt, 0.f, NG);
    out_head_kernel<<<(Nv + 7) / 8, 256>>>(tmp, w2, b2, batch, gsum, gcnt, Nv);
    finalize_kernel<<<(NG + 255) / 256, 256>>>(gsum, gcnt, out, NG);
}

// round 9
// speedup vs baseline: 1.3136x; 1.0747x over previous
#include <cuda_runtime.h>
#include <cuda_bf16.h>
#include <math.h>
#include <stdint.h>

#define HC 128
#define NVMAX 50000
#define NEMAX 400000
#define NG 512
#define LAYERS 2
#define NW 24

// packed weight image: [n][k] bf16, row stride 136 (pad 8), hi then lo
#define WROW 136
#define WIMG_ELEMS (128 * WROW)            // 17408 bf16 per (hi|lo) image
#define WIMG_BYTES (WIMG_ELEMS * 2)        // 34816 B
#define AIMG_BYTES (64 * WROW * 2)         // 17408 B per (hi|lo), 64-row tile

// ---------------- scratch (device globals; no allocation) ----------------
__device__ float g_xs0[NVMAX * HC];
__device__ float g_xs1[NVMAX * HC];
__device__ float g_tmp[NVMAX * HC];
__device__ float g_kt0[NVMAX * HC];
__device__ float g_vt0[NVMAX * HC];
__device__ float g_kt1[NVMAX * HC];
__device__ float g_vt1[NVMAX * HC];
__device__ float g_qe0[NVMAX * HC];   // Q of con nodes (dst of et=0)
__device__ float g_qe1[NVMAX * HC];   // Q of var nodes (dst of et=1)
__device__ float g_aggv[NVMAX * HC];
__device__ float g_aggc[NVMAX * HC];
__device__ __align__(16) __nv_bfloat16 g_wimg[NW * 2 * WIMG_ELEMS];
__device__ float g_bcomp[8 * HC];
__device__ float g_gsum[NG * 2];
__device__ float g_gcnt[NG];
// CSR scratch (seg0: dst=con, seg1: dst=var)
__device__ int g_cnt0[NVMAX], g_cnt1[NVMAX];
__device__ int g_rp0[NVMAX + 1], g_rp1[NVMAX + 1];
__device__ int g_of0[NVMAX + 1], g_of1[NVMAX + 1];
__device__ int g_ss0[NEMAX], g_ss1[NEMAX];

// ---------------- helpers ----------------
__device__ __forceinline__ uint32_t smem_u32(const void* p) {
    uint32_t a;
    asm("{ .reg .u64 t; cvta.to.shared.u64 t, %1; cvt.u32.u64 %0, t; }" : "=r"(a) : "l"(p));
    return a;
}
__device__ __forceinline__ void bsplit(float x, __nv_bfloat16& h, __nv_bfloat16& l) {
    h = __float2bfloat16(x);
    l = __float2bfloat16(x - __bfloat162float(h));
}
__device__ __forceinline__ float gelu_exact(float x) {
    return 0.5f * x * (1.f + erff(x * 0.70710678118654752440f));
}
__device__ __forceinline__ void ldm_x4(uint32_t* r, uint32_t addr) {
    asm volatile("ldmatrix.sync.aligned.m8n8.x4.shared.b16 {%0,%1,%2,%3}, [%4];"
                 : "=r"(r[0]), "=r"(r[1]), "=r"(r[2]), "=r"(r[3]) : "r"(addr));
}
__device__ __forceinline__ void mma16816(float* c, const uint32_t* a, const uint32_t* b) {
    asm volatile("mma.sync.aligned.m16n8k16.row.col.f32.bf16.bf16.f32 "
                 "{%0,%1,%2,%3}, {%4,%5,%6,%7}, {%8,%9}, {%0,%1,%2,%3};"
                 : "+f"(c[0]), "+f"(c[1]), "+f"(c[2]), "+f"(c[3])
                 : "r"(a[0]), "r"(a[1]), "r"(a[2]), "r"(a[3]), "r"(b[0]), "r"(b[1]));
}
__device__ __forceinline__ void cp_async16(uint32_t saddr, const void* gaddr) {
    asm volatile("cp.async.cg.shared.global [%0], [%1], 16;" :: "r"(saddr), "l"(gaddr));
}

// ---------------- weight pre-pack ----------------
struct PackJobs {
    const float* w[NW];
    const float* rel[NW];
    const float* bin[NW];
    float* bout[NW];
};

__global__ void pack_kernel(PackJobs jobs, __nv_bfloat16* img) {
    int j = blockIdx.x;
    int part = blockIdx.y;
    int tid = threadIdx.x;
    const float* w = jobs.w[j];
    const float* rel = jobs.rel[j];
    __shared__ float rs[4096];
    if (rel) {
        for (int i = tid; i < 4096; i += 256) rs[i] = rel[i];
        __syncthreads();
    }
    __nv_bfloat16* ih = img + (size_t)j * 2 * WIMG_ELEMS;
    __nv_bfloat16* il = ih + WIMG_ELEMS;
    for (int idx = part * 4096 + tid; idx < (part + 1) * 4096; idx += 256) {
        int k = idx >> 7, n = idx & 127;
        float val;
        if (rel) {
            int h = n >> 5, nn = n & 31;
            const float* wr = w + k * 128 + h * 32;
            const float* rr = rs + h * 1024 + nn;
            float s = 0.f;
#pragma unroll
            for (int jj = 0; jj < 32; jj++) s += wr[jj] * rr[jj * 32];
            val = s;
        } else {
            val = w[k * 128 + n];
        }
        __nv_bfloat16 h, l;
        bsplit(val, h, l);
        ih[n * WROW + k] = h;
        il[n * WROW + k] = l;
    }
    if (part == 0 && rel && jobs.bout[j] && tid < 128) {
        int h = tid >> 5, nn = tid & 31;
        const float* b = jobs.bin[j];
        float s = 0.f;
#pragma unroll
        for (int jj = 0; jj < 32; jj++) s += b[h * 32 + jj] * rs[h * 1024 + jj * 32 + nn];
        jobs.bout[j][tid] = s;
    }
}

// ---------------- shared GEMM pieces ----------------
#define SM_A 0
#define SM_W (2 * AIMG_BYTES)              // 34816
#define SMEM_MM (2 * AIMG_BYTES + 2 * WIMG_BYTES)   // 104448

// convert 64-row fp32 A tile -> smem bf16 hi/lo (256 threads); GELU optional
template <bool GELU>
__device__ __forceinline__ void convert_A64(const float* __restrict__ A, int row0, int N,
                                            char* smem, int tid) {
#pragma unroll
    for (int it = 0; it < 8; ++it) {
        int i = tid + it * 256;
        int r = i >> 5;
        int k = (i & 31) * 4;
        float4 av = make_float4(0.f, 0.f, 0.f, 0.f);
        int row = row0 + r;
        if (row < N) av = *(const float4*)(A + (size_t)row * HC + k);
        if (GELU) {
            av.x = gelu_exact(av.x); av.y = gelu_exact(av.y);
            av.z = gelu_exact(av.z); av.w = gelu_exact(av.w);
        }
        __nv_bfloat162 h01 = __float22bfloat162_rn(make_float2(av.x, av.y));
        __nv_bfloat162 h23 = __float22bfloat162_rn(make_float2(av.z, av.w));
        float2 f01 = __bfloat1622float2(h01);
        float2 f23 = __bfloat1622float2(h23);
        __nv_bfloat162 l01 = __float22bfloat162_rn(make_float2(av.x - f01.x, av.y - f01.y));
        __nv_bfloat162 l23 = __float22bfloat162_rn(make_float2(av.z - f23.x, av.w - f23.y));
        uint32_t off = (uint32_t)(r * WROW + k) * 2;
        *(uint2*)(smem + SM_A + off) = make_uint2(*(uint32_t*)&h01, *(uint32_t*)&h23);
        *(uint2*)(smem + SM_A + AIMG_BYTES + off) = make_uint2(*(uint32_t*)&l01, *(uint32_t*)&l23);
    }
}

__device__ __forceinline__ void load_W_async(uint32_t sb, const __nv_bfloat16* Wimg, int tid) {
#pragma unroll
    for (int j = 0; j < 17; j++) {
        int i = tid + j * 256;
        if (i < 4352) cp_async16(sb + SM_W + i * 16, (const float4*)Wimg + i);
    }
    asm volatile("cp.async.commit_group;" ::: "memory");
}

__device__ __forceinline__ void mma_tile3(uint32_t a_lane, uint32_t b_lane, float acc[2][4][4]) {
#pragma unroll
    for (int i = 0; i < 2; i++)
#pragma unroll
        for (int j = 0; j < 4; j++)
#pragma unroll
            for (int q = 0; q < 4; q++) acc[i][j][q] = 0.f;
#pragma unroll
    for (int p = 0; p < 3; p++) {
        uint32_t abase = a_lane + (p == 2 ? (uint32_t)AIMG_BYTES : 0u);
        uint32_t bbase = b_lane + (p == 1 ? (uint32_t)WIMG_BYTES : 0u);
#pragma unroll
        for (int ks = 0; ks < 8; ks++) {
            uint32_t ar[2][4], br[2][4];
            ldm_x4(ar[0], abase + ks * 32);
            ldm_x4(ar[1], abase + ks * 32 + 16 * WROW * 2);
            ldm_x4(br[0], bbase + ks * 32);
            ldm_x4(br[1], bbase + ks * 32 + 16 * WROW * 2);
#pragma unroll
            for (int mt = 0; mt < 2; mt++) {
                mma16816(acc[mt][0], ar[mt], br[0] + 0);
                mma16816(acc[mt][1], ar[mt], br[0] + 2);
                mma16816(acc[mt][2], ar[mt], br[1] + 0);
                mma16816(acc[mt][3], ar[mt], br[1] + 2);
            }
        }
    }
}

// ---------------- chain GEMM kernel (1..3 steps, shared A tile) --------------
struct ChainP {
    const float* A;
    const __nv_bfloat16* W[3];
    const float* bias[3];
    float* Cg[3];     // non-null => write global; null => chain result into smem A
    int relu[3];
    int nsteps;
    int N;
};

__global__ void __launch_bounds__(256, 2)
chain_kernel(ChainP P) {
    extern __shared__ char smem[];
    int tid = threadIdx.x;
    int wid = tid >> 5;
    int lane = tid & 31;
    int row0 = blockIdx.x * 64;
    uint32_t sb = smem_u32(smem);

    load_W_async(sb, P.W[0], tid);
    convert_A64<false>(P.A, row0, P.N, smem, tid);
    asm volatile("cp.async.wait_group 0;" ::: "memory");
    __syncthreads();

    int warpM = wid >> 2;
    int warpN = wid & 3;
    uint32_t a_lane = sb + SM_A +
        ((uint32_t)((warpM * 32 + (lane & 15)) * WROW + ((lane >> 4) << 3)) << 1);
    uint32_t b_lane = sb + SM_W +
        ((uint32_t)((warpN * 32 + (lane & 7) + ((lane >> 4) << 3)) * WROW +
                    (((lane >> 3) & 1) << 3)) << 1);
    int gid = lane >> 2, tq = lane & 3;

    for (int s = 0; s < P.nsteps; s++) {
        float acc[2][4][4];
        mma_tile3(a_lane, b_lane, acc);
        bool last = (s + 1 == P.nsteps);
        __syncthreads();                 // all warps done reading W (and A)
        if (!last) load_W_async(sb, P.W[s + 1], tid);

        const float* bias = P.bias[s];
        float* Cg = P.Cg[s];
        int rl = P.relu[s];
#pragma unroll
        for (int mt = 0; mt < 2; mt++) {
#pragma unroll
            for (int nt = 0; nt < 4; nt++) {
                int col = warpN * 32 + nt * 8 + tq * 2;
                float2 bv = *(const float2*)(bias + col);
#pragma unroll
                for (int half = 0; half < 2; half++) {
                    int rloc = warpM * 32 + mt * 16 + gid + half * 8;
                    float c0 = acc[mt][nt][half * 2 + 0] + bv.x;
                    float c1 = acc[mt][nt][half * 2 + 1] + bv.y;
                    if (rl) { c0 = fmaxf(c0, 0.f); c1 = fmaxf(c1, 0.f); }
                    if (Cg) {
                        int row = row0 + rloc;
                        if (row < P.N)
                            *(float2*)(Cg + (size_t)row * HC + col) = make_float2(c0, c1);
                    } else {
                        __nv_bfloat162 h2 = __float22bfloat162_rn(make_float2(c0, c1));
                        float2 hf = __bfloat1622float2(h2);
                        __nv_bfloat162 l2 =
                            __float22bfloat162_rn(make_float2(c0 - hf.x, c1 - hf.y));
                        uint32_t off = (uint32_t)(rloc * WROW + col) * 2;
                        *(uint32_t*)(smem + SM_A + off) = *(uint32_t*)&h2;
                        *(uint32_t*)(smem + SM_A + AIMG_BYTES + off) = *(uint32_t*)&l2;
                    }
                }
            }
        }
        if (!last) {
            asm volatile("cp.async.wait_group 0;" ::: "memory");
            __syncthreads();             // W[s+1] + chained A stores visible
        }
    }
}

// ---------------- gated GEMM (agg pre-normalized; gelu in convert) -----------
__global__ void __launch_bounds__(256, 2)
mm_gated_kernel(const float* __restrict__ A, const __nv_bfloat16* __restrict__ Wimg,
                const float* __restrict__ bias, float* __restrict__ C, int N,
                const float* __restrict__ gate_p, const float* __restrict__ xprev) {
    extern __shared__ char smem[];
    int tid = threadIdx.x;
    int wid = tid >> 5;
    int lane = tid & 31;
    int row0 = blockIdx.x * 64;
    uint32_t sb = smem_u32(smem);

    load_W_async(sb, Wimg, tid);
    convert_A64<true>(A, row0, N, smem, tid);
    asm volatile("cp.async.wait_group 0;" ::: "memory");
    __syncthreads();

    int warpM = wid >> 2;
    int warpN = wid & 3;
    uint32_t a_lane = sb + SM_A +
        ((uint32_t)((warpM * 32 + (lane & 15)) * WROW + ((lane >> 4) << 3)) << 1);
    uint32_t b_lane = sb + SM_W +
        ((uint32_t)((warpN * 32 + (lane & 7) + ((lane >> 4) << 3)) * WROW +
                    (((lane >> 3) & 1) << 3)) << 1);

    float acc[2][4][4];
    mma_tile3(a_lane, b_lane, acc);

    int gid = lane >> 2, tq = lane & 3;
    float g = 1.f / (1.f + expf(-*gate_p));
    float og = 1.f - g;
#pragma unroll
    for (int mt = 0; mt < 2; mt++) {
#pragma unroll
        for (int nt = 0; nt < 4; nt++) {
            int col = warpN * 32 + nt * 8 + tq * 2;
            float2 bv = *(const float2*)(bias + col);
#pragma unroll
            for (int half = 0; half < 2; half++) {
                int row = row0 + warpM * 32 + mt * 16 + gid + half * 8;
                if (row >= N) continue;
                float c0 = acc[mt][nt][half * 2 + 0] + bv.x;
                float c1 = acc[mt][nt][half * 2 + 1] + bv.y;
                float2 xp = *(const float2*)(xprev + (size_t)row * HC + col);
                c0 = g * c0 + og * xp.x;
                c1 = g * c1 + og * xp.y;
                *(float2*)(C + (size_t)row * HC + col) = make_float2(c0, c1);
            }
        }
    }
}

// ---------------- CSR build (once per launch; reused for both layers) --------
__global__ void clear_cnt_kernel(int* c0, int n0, int* c1, int n1) {
    int i = blockIdx.x * blockDim.x + threadIdx.x;
    if (i < n0) c0[i] = 0;
    if (i < n1) c1[i] = 0;
}

__global__ void hist_kernel(const int* d0, int E0, int* c0,
                            const int* d1, int E1, int* c1) {
    int e = blockIdx.x * blockDim.x + threadIdx.x;
    if (e < E0) atomicAdd(&c0[d0[e]], 1);
    if (e < E1) atomicAdd(&c1[d1[e]], 1);
}

__global__ void scan_kernel(const int* c0, int n0, int* r0, int* o0,
                            const int* c1, int n1, int* r1, int* o1) {
    const int* cnt = blockIdx.x ? c1 : c0;
    int n = blockIdx.x ? n1 : n0;
    int* rp = blockIdx.x ? r1 : r0;
    int* of = blockIdx.x ? o1 : o0;
    __shared__ int sh[1024];
    __shared__ int carrysh;
    int tid = threadIdx.x;
    if (tid == 0) { carrysh = 0; rp[0] = 0; of[0] = 0; }
    __syncthreads();
    for (int base = 0; base < n; base += 1024) {
        int i = base + tid;
        sh[tid] = (i < n) ? cnt[i] : 0;
        __syncthreads();
#pragma unroll
        for (int off = 1; off < 1024; off <<= 1) {
            int t = (tid >= off) ? sh[tid - off] : 0;
            __syncthreads();
            sh[tid] += t;
            __syncthreads();
        }
        int inc = sh[tid] + carrysh;
        if (i < n) { rp[i + 1] = inc; of[i + 1] = inc; }
        __syncthreads();
        if (tid == 1023) carrysh = inc;
        __syncthreads();
    }
}

__global__ void scatter_kernel(const int* s0, const int* d0, int E0, int* o0, int* ss0,
                               const int* s1, const int* d1, int E1, int* o1, int* ss1) {
    int e = blockIdx.x * blockDim.x + threadIdx.x;
    if (e < E0) { int p = atomicAdd(&o0[d0[e]], 1); ss0[p] = s0[e]; }
    if (e < E1) { int p = atomicAdd(&o1[d1[e]], 1); ss1[p] = s1[e]; }
}

// ---------------- CSR attention: warp per dst, normalized output -------------
struct CsrP {
    const float* q[2];
    const float* kt[2];
    const float* vt[2];
    const int* rowptr[2];
    const int* ssrc[2];
    const float* prel[2];
    float* agg[2];
    int Nd0, Ndtot;
};

__global__ void attn_csr_kernel(CsrP P) {
    int w = blockIdx.x * 8 + (threadIdx.x >> 5);
    if (w >= P.Ndtot) return;
    int seg = w >= P.Nd0;
    int d = w - (seg ? P.Nd0 : 0);
    int lane = threadIdx.x & 31;
    int h = lane >> 3;
    const int* rp = P.rowptr[seg];
    int beg = rp[d], end = rp[d + 1];
    float pr = P.prel[seg][h] * 0.17677669529663687f;
    float4 qv = *(const float4*)(P.q[seg] + (size_t)d * HC + lane * 4);
    const float* kt = P.kt[seg];
    const float* vt = P.vt[seg];
    const int* ss = P.ssrc[seg];
    float4 acc = make_float4(0.f, 0.f, 0.f, 0.f);
    float den = 0.f;
    for (int i = beg; i < end; i++) {
        int s = ss[i];
        float4 kv = *(const float4*)(kt + (size_t)s * HC + lane * 4);
        float4 vv = *(const float4*)(vt + (size_t)s * HC + lane * 4);
        float p = qv.x * kv.x + qv.y * kv.y + qv.z * kv.z + qv.w * kv.w;
        p += __shfl_xor_sync(0xffffffffu, p, 1);
        p += __shfl_xor_sync(0xffffffffu, p, 2);
        p += __shfl_xor_sync(0xffffffffu, p, 4);   // all lanes of 8-group hold head sum
        float ex = expf(p * pr);
        den += ex;
        acc.x += ex * vv.x; acc.y += ex * vv.y;
        acc.z += ex * vv.z; acc.w += ex * vv.w;
    }
    float rcp = (den > 0.f) ? 1.f / den : 0.f;
    acc.x *= rcp; acc.y *= rcp; acc.z *= rcp; acc.w *= rcp;
    *(float4*)(P.agg[seg] + (size_t)d * HC + lane * 4) = acc;
}

// ---------------- output head ----------------
__global__ void out_head_kernel(const float* __restrict__ X, const float* __restrict__ W2,
                                const float* __restrict__ b2, const int* __restrict__ batch,
                                float* __restrict__ gsum, float* __restrict__ gcnt, int N) {
    int n = blockIdx.x * 8 + (threadIdx.x >> 5);
    if (n >= N) return;
    int lane = threadIdx.x & 31;
    float4 x = *(const float4*)(X + (size_t)n * HC + lane * 4);
    float4 wa = *(const float4*)(W2 + lane * 8);
    float4 wb = *(const float4*)(W2 + lane * 8 + 4);
    float p0 = x.x * wa.x + x.y * wa.z + x.z * wb.x + x.w * wb.z;
    float p1 = x.x * wa.y + x.y * wa.w + x.z * wb.y + x.w * wb.w;
#pragma unroll
    for (int off = 16; off > 0; off >>= 1) {
        p0 += __shfl_xor_sync(0xffffffffu, p0, off);
        p1 += __shfl_xor_sync(0xffffffffu, p1, off);
    }
    if (lane == 0) {
        float l0 = p0 + b2[0], l1 = p1 + b2[1];
        float m = fmaxf(l0, l1);
        float e0 = expf(l0 - m), e1 = expf(l1 - m);
        float inv = 1.f / (e0 + e1);
        int g = batch[n];
        atomicAdd(&gsum[g * 2 + 0], e0 * inv);
        atomicAdd(&gsum[g * 2 + 1], e1 * inv);
        atomicAdd(&gcnt[g], 1.f);
    }
}

__global__ void finalize_kernel(const float* __restrict__ gsum, const float* __restrict__ gcnt,
                                float* __restrict__ out, int G) {
    int g = blockIdx.x * blockDim.x + threadIdx.x;
    if (g >= G) return;
    float c = fmaxf(gcnt[g], 1.f);
    out[g * 2 + 0] = gsum[g * 2 + 0] / c;
    out[g * 2 + 1] = gsum[g * 2 + 1] / c;
}

__global__ void fill_kernel(float* __restrict__ p, float v, int n) {
    int i = blockIdx.x * blockDim.x + threadIdx.x;
    if (i < n) p[i] = v;
}

// ---------------- host orchestration ----------------
static inline void fillf(float* p, float v, int n) {
    fill_kernel<<<(n + 255) / 256, 256>>>(p, v, n);
}

extern "C" void kernel_launch(void* const* d_in, const int* in_sizes, int n_in,
                              void* d_out, int out_size) {
    const float* x_var = (const float*)d_in[0];
    const float* x_con = (const float*)d_in[1];
    const float* mlp_in_w = (const float*)d_in[2];
    const float* mlp_in_b = (const float*)d_in[3];
    const float* w0 = (const float*)d_in[4];
    const float* b0 = (const float*)d_in[5];
    const float* w1 = (const float*)d_in[6];
    const float* b1 = (const float*)d_in[7];
    const float* w2 = (const float*)d_in[8];
    const float* b2 = (const float*)d_in[9];
    const float* k_w = (const float*)d_in[10];
    const float* k_b = (const float*)d_in[11];
    const float* q_w = (const float*)d_in[12];
    const float* q_b = (const float*)d_in[13];
    const float* v_w = (const float*)d_in[14];
    const float* v_b = (const float*)d_in[15];
    const float* a_w = (const float*)d_in[16];
    const float* a_b = (const float*)d_in[17];
    const float* skip = (const float*)d_in[18];
    const float* a_rel = (const float*)d_in[19];
    const float* m_rel = (const float*)d_in[20];
    const float* p_rel = (const float*)d_in[21];
    const int* evc = (const int*)d_in[22];
    const int* ecv = (const int*)d_in[23];
    const int* batch = (const int*)d_in[24];
    float* out = (float*)d_out;

    int Nv = in_sizes[0] / HC;
    int Nc = in_sizes[1] / HC;
    int Evc = in_sizes[22] / 2;
    int Ecv = in_sizes[23] / 2;

    float *xs0, *xs1, *tmp, *kt0, *vt0, *kt1, *vt1, *qe0, *qe1, *aggv, *aggc;
    float *bcomp, *gsum, *gcnt;
    int *cnt0, *cnt1, *rp0, *rp1, *of0, *of1, *ss0, *ss1;
    __nv_bfloat16* wimg;
    cudaGetSymbolAddress((void**)&xs0, g_xs0);
    cudaGetSymbolAddress((void**)&xs1, g_xs1);
    cudaGetSymbolAddress((void**)&tmp, g_tmp);
    cudaGetSymbolAddress((void**)&kt0, g_kt0);
    cudaGetSymbolAddress((void**)&vt0, g_vt0);
    cudaGetSymbolAddress((void**)&kt1, g_kt1);
    cudaGetSymbolAddress((void**)&vt1, g_vt1);
    cudaGetSymbolAddress((void**)&qe0, g_qe0);
    cudaGetSymbolAddress((void**)&qe1, g_qe1);
    cudaGetSymbolAddress((void**)&aggv, g_aggv);
    cudaGetSymbolAddress((void**)&aggc, g_aggc);
    cudaGetSymbolAddress((void**)&wimg, g_wimg);
    cudaGetSymbolAddress((void**)&bcomp, g_bcomp);
    cudaGetSymbolAddress((void**)&gsum, g_gsum);
    cudaGetSymbolAddress((void**)&gcnt, g_gcnt);
    cudaGetSymbolAddress((void**)&cnt0, g_cnt0);
    cudaGetSymbolAddress((void**)&cnt1, g_cnt1);
    cudaGetSymbolAddress((void**)&rp0, g_rp0);
    cudaGetSymbolAddress((void**)&rp1, g_rp1);
    cudaGetSymbolAddress((void**)&of0, g_of0);
    cudaGetSymbolAddress((void**)&of1, g_of1);
    cudaGetSymbolAddress((void**)&ss0, g_ss0);
    cudaGetSymbolAddress((void**)&ss1, g_ss1);

    cudaFuncSetAttribute(chain_kernel, cudaFuncAttributeMaxDynamicSharedMemorySize, SMEM_MM);
    cudaFuncSetAttribute(mm_gated_kernel, cudaFuncAttributeMaxDynamicSharedMemorySize, SMEM_MM);

    // ---- weight packing ----
    PackJobs pj;
    for (int j = 0; j < NW; j++) { pj.w[j] = nullptr; pj.rel[j] = nullptr; pj.bin[j] = nullptr; pj.bout[j] = nullptr; }
    for (int t = 0; t < 2; t++)
        for (int i = 0; i < 3; i++) pj.w[t * 3 + i] = mlp_in_w + (size_t)(t * 3 + i) * 16384;
    for (int li = 0; li < 4; li++) {
        pj.w[6 + li] = k_w + (size_t)li * 16384;
        pj.rel[6 + li] = a_rel + (size_t)li * 4096;
        pj.bin[6 + li] = k_b + (size_t)li * 128;
        pj.bout[6 + li] = bcomp + (size_t)li * 128;
        pj.w[10 + li] = v_w + (size_t)li * 16384;
        pj.rel[10 + li] = m_rel + (size_t)li * 4096;
        pj.bin[10 + li] = v_b + (size_t)li * 128;
        pj.bout[10 + li] = bcomp + (size_t)(4 + li) * 128;
        pj.w[14 + li] = q_w + (size_t)li * 16384;
        pj.w[18 + li] = a_w + (size_t)li * 16384;
    }
    pj.w[22] = w0;
    pj.w[23] = w1;
    pack_kernel<<<dim3(NW, 4), 256>>>(pj, wimg);

#define IMG(j) (wimg + (size_t)(j) * 2 * WIMG_ELEMS)

    // ---- CSR build (seg0: dst=con, seg1: dst=var) ----
    {
        int mx = (Nv > Nc ? Nv : Nc);
        clear_cnt_kernel<<<(mx + 255) / 256, 256>>>(cnt0, Nc, cnt1, Nv);
        int me = (Evc > Ecv ? Evc : Ecv);
        hist_kernel<<<(me + 255) / 256, 256>>>(evc + Evc, Evc, cnt0, ecv + Ecv, Ecv, cnt1);
        scan_kernel<<<2, 1024>>>(cnt0, Nc, rp0, of0, cnt1, Nv, rp1, of1);
        scatter_kernel<<<(me + 255) / 256, 256>>>(evc, evc + Evc, Evc, of0, ss0,
                                                  ecv, ecv + Ecv, Ecv, of1, ss1);
    }

    // ---- input MLPs: one 3-step chain per node type ----
    for (int t = 0; t < 2; t++) {
        ChainP c{};
        c.A = (t == 0) ? x_var : x_con;
        c.N = (t == 0) ? Nv : Nc;
        c.nsteps = 3;
        for (int i = 0; i < 3; i++) {
            c.W[i] = IMG(t * 3 + i);
            c.bias[i] = mlp_in_b + (size_t)(t * 3 + i) * 128;
            c.Cg[i] = nullptr;
            c.relu[i] = (i < 2);
        }
        c.Cg[2] = (t == 0) ? xs0 : xs1;
        chain_kernel<<<(c.N + 63) / 64, 256, SMEM_MM>>>(c);
    }

    // ---- HGTConv layers ----
    for (int l = 0; l < LAYERS; l++) {
        int li0 = l * 2 + 0, li1 = l * 2 + 1;

        // K+V+Q 3-step chain per type (shared A-convert; Q of type t feeds qe(1-t))
        for (int t = 0; t < 2; t++) {
            int li = (t == 0) ? li0 : li1;
            ChainP c{};
            c.A = (t == 0) ? xs0 : xs1;
            c.N = (t == 0) ? Nv : Nc;
            c.nsteps = 3;
            c.W[0] = IMG(6 + li);  c.bias[0] = bcomp + (size_t)li * 128;
            c.Cg[0] = (t == 0) ? kt0 : kt1;  c.relu[0] = 0;
            c.W[1] = IMG(10 + li); c.bias[1] = bcomp + (size_t)(4 + li) * 128;
            c.Cg[1] = (t == 0) ? vt0 : vt1;  c.relu[1] = 0;
            c.W[2] = IMG(14 + li); c.bias[2] = q_b + (size_t)li * 128;
            c.Cg[2] = (t == 0) ? qe1 : qe0;  c.relu[2] = 0;
            chain_kernel<<<(c.N + 63) / 64, 256, SMEM_MM>>>(c);
        }

        // CSR attention (both edge types; writes normalized agg, zeros for empty)
        CsrP cp{};
        cp.q[0] = qe0; cp.kt[0] = kt0; cp.vt[0] = vt0;
        cp.rowptr[0] = rp0; cp.ssrc[0] = ss0;
        cp.prel[0] = p_rel + (size_t)li0 * 4;
        cp.agg[0] = aggc;
        cp.q[1] = qe1; cp.kt[1] = kt1; cp.vt[1] = vt1;
        cp.rowptr[1] = rp1; cp.ssrc[1] = ss1;
        cp.prel[1] = p_rel + (size_t)li1 * 4;
        cp.agg[1] = aggv;
        cp.Nd0 = Nc; cp.Ndtot = Nc + Nv;
        attn_csr_kernel<<<(cp.Ndtot + 7) / 8, 256>>>(cp);

        // gated update
        mm_gated_kernel<<<(Nv + 63) / 64, 256, SMEM_MM>>>(
            aggv, IMG(18 + li0), a_b + (size_t)li0 * 128, xs0, Nv, skip + li0, xs0);
        mm_gated_kernel<<<(Nc + 63) / 64, 256, SMEM_MM>>>(
            aggc, IMG(18 + li1), a_b + (size_t)li1 * 128, xs1, Nc, skip + li1, xs1);
    }

    // ---- output head: 2-step chain then head reduce ----
    {
        ChainP c{};
        c.A = xs0; c.N = Nv; c.nsteps = 2;
        c.W[0] = IMG(22); c.bias[0] = b0; c.Cg[0] = nullptr; c.relu[0] = 1;
        c.W[1] = IMG(23); c.bias[1] = b1; c.Cg[1] = tmp; c.relu[1] = 1;
        chain_kernel<<<(Nv + 63) / 64, 256, SMEM_MM>>>(c);
    }
    fillf(gsum, 0.f, NG * 2);
    fillf(gcnt, 0.f, NG);
    out_head_kernel<<<(Nv + 7) / 8, 256>>>(tmp, w2, b2, batch, gsum, gcnt, Nv);
    finalize_kernel<<<(NG + 255) / 256, 256>>>(gsum, gcnt, out, NG);
}